// round 1
// baseline (speedup 1.0000x reference)
#include <cuda_runtime.h>
#include <math.h>
#include <stdint.h>

#define LQ 1024
#define BZ 8
#define D  512
#define NH 8
#define DH 64

#define IOU_THR 0.2f
#define COS_THR 0.2f

// ---------------- scratch (static device globals; no allocations) ----------
__device__ float g_Q[(size_t)BZ * LQ * D];                 // 16 MB
__device__ float g_K[(size_t)BZ * LQ * D];                 // 16 MB
__device__ float g_V[(size_t)BZ * LQ * D];                 // 16 MB
__device__ float g_norm[BZ * LQ];
__device__ unsigned char g_mask[(size_t)BZ * LQ * LQ];     // 8 MB  (1 = masked)
__device__ float g_S[(size_t)BZ * NH * LQ * LQ];           // 256 MB scores/probs

// ---------------- reduction helpers ----------------------------------------
__device__ __forceinline__ float warp_max(float v) {
#pragma unroll
    for (int o = 16; o > 0; o >>= 1) v = fmaxf(v, __shfl_xor_sync(0xffffffffu, v, o));
    return v;
}
__device__ __forceinline__ float warp_sum(float v) {
#pragma unroll
    for (int o = 16; o > 0; o >>= 1) v += __shfl_xor_sync(0xffffffffu, v, o);
    return v;
}

// ---------------- row norms of h = transpose(query) -------------------------
// h[b][l][k] = query[(l*BZ + b)*D + k]
__global__ void norm_kernel(const float* __restrict__ q) {
    int row = blockIdx.x;              // b*LQ + l
    int b = row / LQ, l = row % LQ;
    const float* h = q + ((size_t)l * BZ + b) * D;
    float s = 0.f;
    for (int k = threadIdx.x; k < D; k += 128) {
        float v = h[k];
        s = fmaf(v, v, s);
    }
    __shared__ float red[4];
    s = warp_sum(s);
    int wid = threadIdx.x >> 5, lane = threadIdx.x & 31;
    if (lane == 0) red[wid] = s;
    __syncthreads();
    if (threadIdx.x == 0) {
        float t = red[0] + red[1] + red[2] + red[3];
        g_norm[row] = fmaxf(sqrtf(t), 1e-8f);
    }
}

// ---------------- shared 64x64x16 fp32 GEMM micro-kernel pieces -------------
__device__ __forceinline__ void mma16(const float (*As)[64], const float (*Bs)[64],
                                      int ty, int tx, float (&acc)[4][4]) {
#pragma unroll
    for (int k = 0; k < 16; ++k) {
        float4 a = *(const float4*)&As[k][ty << 2];
        float4 bb = *(const float4*)&Bs[k][tx << 2];
        float av[4] = {a.x, a.y, a.z, a.w};
        float bv[4] = {bb.x, bb.y, bb.z, bb.w};
#pragma unroll
        for (int i = 0; i < 4; i++)
#pragma unroll
            for (int j = 0; j < 4; j++)
                acc[i][j] = fmaf(av[i], bv[j], acc[i][j]);
    }
}

// ---------------- projections: C[b,i,n] = sum_k h[b,i,k] * W[n,k] + bias[n] -
__global__ void proj_kernel(const float* __restrict__ q,
                            const float* __restrict__ W,
                            const float* __restrict__ bias,
                            int which) {
    __shared__ float As[16][64];
    __shared__ float Bs[16][64];
    float* out = (which == 0) ? g_Q : (which == 1) ? g_K : g_V;

    const int b = blockIdx.z;
    const int row0 = blockIdx.y * 64;
    const int col0 = blockIdx.x * 64;
    const int tid = threadIdx.x;
    const int tx = tid & 15, ty = tid >> 4;
    const int lr = tid >> 2;            // 0..63  loader row
    const int lc = (tid & 3) << 2;      // 0,4,8,12 loader k offset

    const float* Abase = q + (size_t)b * D + (size_t)(row0 + lr) * (BZ * D) + lc;
    const float* Bbase = W + (size_t)(col0 + lr) * D + lc;

    float acc[4][4] = {};
    for (int kk = 0; kk < D; kk += 16) {
        float4 a4 = *(const float4*)(Abase + kk);
        float4 b4 = *(const float4*)(Bbase + kk);
        As[lc + 0][lr] = a4.x; As[lc + 1][lr] = a4.y;
        As[lc + 2][lr] = a4.z; As[lc + 3][lr] = a4.w;
        Bs[lc + 0][lr] = b4.x; Bs[lc + 1][lr] = b4.y;
        Bs[lc + 2][lr] = b4.z; Bs[lc + 3][lr] = b4.w;
        __syncthreads();
        mma16(As, Bs, ty, tx, acc);
        __syncthreads();
    }
#pragma unroll
    for (int i = 0; i < 4; i++) {
        int r = row0 + (ty << 2) + i;
#pragma unroll
        for (int j = 0; j < 4; j++) {
            int c = col0 + (tx << 2) + j;
            out[((size_t)b * LQ + r) * D + c] = acc[i][j] + bias[c];
        }
    }
}

// ---------------- h.h^T GEMM + cos/iou mask build ---------------------------
__global__ void mask_kernel(const float* __restrict__ q,
                            const float* __restrict__ seg) {
    __shared__ float As[16][64];
    __shared__ float Bs[16][64];
    const int b = blockIdx.z;
    const int row0 = blockIdx.y * 64;
    const int col0 = blockIdx.x * 64;
    const int tid = threadIdx.x;
    const int tx = tid & 15, ty = tid >> 4;
    const int lr = tid >> 2;
    const int lc = (tid & 3) << 2;

    const float* Abase = q + (size_t)b * D + (size_t)(row0 + lr) * (BZ * D) + lc;
    const float* Bbase = q + (size_t)b * D + (size_t)(col0 + lr) * (BZ * D) + lc;

    float acc[4][4] = {};
    for (int kk = 0; kk < D; kk += 16) {
        float4 a4 = *(const float4*)(Abase + kk);
        float4 b4 = *(const float4*)(Bbase + kk);
        As[lc + 0][lr] = a4.x; As[lc + 1][lr] = a4.y;
        As[lc + 2][lr] = a4.z; As[lc + 3][lr] = a4.w;
        Bs[lc + 0][lr] = b4.x; Bs[lc + 1][lr] = b4.y;
        Bs[lc + 2][lr] = b4.z; Bs[lc + 3][lr] = b4.w;
        __syncthreads();
        mma16(As, Bs, ty, tx, acc);
        __syncthreads();
    }

    // per-thread segment/norm data for its 4 rows & 4 cols
    float rs[4], re[4], rl[4], rn[4];
    float cs[4], ce[4], cl[4], cn[4];
#pragma unroll
    for (int i = 0; i < 4; i++) {
        int r = row0 + (ty << 2) + i;
        float cc = seg[((size_t)b * LQ + r) * 2 + 0];
        float ll = seg[((size_t)b * LQ + r) * 2 + 1];
        rs[i] = cc - 0.5f * ll; re[i] = cc + 0.5f * ll; rl[i] = ll;
        rn[i] = g_norm[b * LQ + r];
        int c = col0 + (tx << 2) + i;
        float cc2 = seg[((size_t)b * LQ + c) * 2 + 0];
        float ll2 = seg[((size_t)b * LQ + c) * 2 + 1];
        cs[i] = cc2 - 0.5f * ll2; ce[i] = cc2 + 0.5f * ll2; cl[i] = ll2;
        cn[i] = g_norm[b * LQ + c];
    }
#pragma unroll
    for (int i = 0; i < 4; i++) {
        int r = row0 + (ty << 2) + i;
#pragma unroll
        for (int j = 0; j < 4; j++) {
            int c = col0 + (tx << 2) + j;
            float cosv = acc[i][j] / (rn[i] * cn[j]);
            float inter = fmaxf(fminf(re[i], ce[j]) - fmaxf(rs[i], cs[j]), 0.f);
            float uni = rl[i] + cl[j] - inter;
            float iou = inter / uni;
            bool adj = (cosv > COS_THR) && ((iou <= IOU_THR) || (r == c));
            g_mask[((size_t)b * LQ + r) * LQ + c] = adj ? 0 : 1;
        }
    }
}

// ---------------- scores: S[b,h,i,j] = Q_h[i].K_h[j] / 8, mask -> -inf ------
__global__ void scores_kernel() {
    __shared__ float As[16][64];
    __shared__ float Bs[16][64];
    const int bh = blockIdx.z;
    const int b = bh >> 3, h = bh & 7;
    const int row0 = blockIdx.y * 64;
    const int col0 = blockIdx.x * 64;
    const int tid = threadIdx.x;
    const int tx = tid & 15, ty = tid >> 4;
    const int lr = tid >> 2;
    const int lc = (tid & 3) << 2;

    const float* Abase = g_Q + ((size_t)b * LQ + row0 + lr) * D + h * DH + lc;
    const float* Bbase = g_K + ((size_t)b * LQ + col0 + lr) * D + h * DH + lc;

    float acc[4][4] = {};
#pragma unroll
    for (int kk = 0; kk < DH; kk += 16) {
        float4 a4 = *(const float4*)(Abase + kk);
        float4 b4 = *(const float4*)(Bbase + kk);
        As[lc + 0][lr] = a4.x; As[lc + 1][lr] = a4.y;
        As[lc + 2][lr] = a4.z; As[lc + 3][lr] = a4.w;
        Bs[lc + 0][lr] = b4.x; Bs[lc + 1][lr] = b4.y;
        Bs[lc + 2][lr] = b4.z; Bs[lc + 3][lr] = b4.w;
        __syncthreads();
        mma16(As, Bs, ty, tx, acc);
        __syncthreads();
    }
    const float NEG_INF = __int_as_float(0xff800000);
#pragma unroll
    for (int i = 0; i < 4; i++) {
        int r = row0 + (ty << 2) + i;
#pragma unroll
        for (int j = 0; j < 4; j++) {
            int c = col0 + (tx << 2) + j;
            float s = acc[i][j] * 0.125f;   // 1/sqrt(64)
            if (g_mask[((size_t)b * LQ + r) * LQ + c]) s = NEG_INF;
            g_S[((size_t)bh * LQ + r) * LQ + c] = s;
        }
    }
}

// ---------------- row softmax over g_S (row length 1024) --------------------
__global__ void softmax_kernel() {
    const size_t row = blockIdx.x;
    float* S = g_S + row * LQ;
    const int tid = threadIdx.x;       // 256 threads
    float v[4];
    float m = __int_as_float(0xff800000);
#pragma unroll
    for (int i = 0; i < 4; i++) {
        v[i] = S[tid + (i << 8)];
        m = fmaxf(m, v[i]);
    }
    __shared__ float redm[8];
    __shared__ float reds[8];
    m = warp_max(m);
    if (!(tid & 31)) redm[tid >> 5] = m;
    __syncthreads();
    float m2 = redm[0];
#pragma unroll
    for (int i = 1; i < 8; i++) m2 = fmaxf(m2, redm[i]);

    float s = 0.f;
#pragma unroll
    for (int i = 0; i < 4; i++) {
        v[i] = __expf(v[i] - m2);
        s += v[i];
    }
    s = warp_sum(s);
    if (!(tid & 31)) reds[tid >> 5] = s;
    __syncthreads();
    float tot = reds[0];
#pragma unroll
    for (int i = 1; i < 8; i++) tot += reds[i];
    float inv = 1.0f / tot;
#pragma unroll
    for (int i = 0; i < 4; i++) S[tid + (i << 8)] = v[i] * inv;
}

// ---------------- O = P @ V_h + residual; write [Lq, bz, d] layout ----------
__global__ void attnv_kernel(const float* __restrict__ q,
                             float* __restrict__ out) {
    __shared__ float As[16][64];
    __shared__ float Bs[16][64];
    const int bh = blockIdx.z;
    const int b = bh >> 3, h = bh & 7;
    const int row0 = blockIdx.y * 64;
    const int tid = threadIdx.x;
    const int tx = tid & 15, ty = tid >> 4;
    const int lr = tid >> 2;            // A loader row 0..63
    const int lc = (tid & 3) << 2;      // A loader k-offset
    const int br = tid >> 4;            // B loader k-row 0..15
    const int bc = (tid & 15) << 2;     // B loader col 0..60

    const float* Abase = g_S + ((size_t)bh * LQ + row0 + lr) * LQ + lc;
    const float* Bbase = g_V + ((size_t)b * LQ + br) * D + h * DH + bc;

    float acc[4][4] = {};
    for (int kk = 0; kk < LQ; kk += 16) {
        float4 a4 = *(const float4*)(Abase + kk);
        float4 b4 = *(const float4*)(Bbase + (size_t)kk * D);
        As[lc + 0][lr] = a4.x; As[lc + 1][lr] = a4.y;
        As[lc + 2][lr] = a4.z; As[lc + 3][lr] = a4.w;
        *(float4*)&Bs[br][bc] = b4;
        __syncthreads();
        mma16(As, Bs, ty, tx, acc);
        __syncthreads();
    }
#pragma unroll
    for (int i = 0; i < 4; i++) {
        int r = row0 + (ty << 2) + i;      // l
#pragma unroll
        for (int j = 0; j < 4; j++) {
            int c = (tx << 2) + j;         // 0..63 within head
            size_t idx = ((size_t)r * BZ + b) * D + h * DH + c;
            out[idx] = q[idx] + acc[i][j];
        }
    }
}

// ---------------- launch ----------------------------------------------------
extern "C" void kernel_launch(void* const* d_in, const int* in_sizes, int n_in,
                              void* d_out, int out_size) {
    const float* query = (const float*)d_in[0];
    const float* seg   = (const float*)d_in[1];
    const float* Wq    = (const float*)d_in[2];
    const float* bq    = (const float*)d_in[3];
    const float* Wk    = (const float*)d_in[4];
    const float* bk    = (const float*)d_in[5];
    const float* Wv    = (const float*)d_in[6];
    const float* bv    = (const float*)d_in[7];
    float* out = (float*)d_out;

    norm_kernel<<<BZ * LQ, 128>>>(query);

    dim3 gproj(D / 64, LQ / 64, BZ);
    proj_kernel<<<gproj, 256>>>(query, Wq, bq, 0);
    proj_kernel<<<gproj, 256>>>(query, Wk, bk, 1);
    proj_kernel<<<gproj, 256>>>(query, Wv, bv, 2);

    dim3 gmask(LQ / 64, LQ / 64, BZ);
    mask_kernel<<<gmask, 256>>>(query, seg);

    dim3 gsc(LQ / 64, LQ / 64, BZ * NH);
    scores_kernel<<<gsc, 256>>>();

    softmax_kernel<<<BZ * NH * LQ, 256>>>();

    dim3 gav(1, LQ / 64, BZ * NH);
    attnv_kernel<<<gav, 256>>>(query, out);
}

// round 4
// speedup vs baseline: 2.1312x; 2.1312x over previous
#include <cuda_runtime.h>
#include <math.h>
#include <stdint.h>

#define LQ 1024
#define BZ 8
#define D  512
#define NH 8
#define DH 64
#define IOU_THR 0.2f
#define COS_THR 0.2f

#define SSTR 36   // smem row stride in floats (bank = (4r+c)%32, conflict-free)

// ---------------- scratch (static device globals; no allocations) ----------
__device__ float g_Q[(size_t)BZ * LQ * D];                 // 16 MB
__device__ float g_K[(size_t)BZ * LQ * D];                 // 16 MB
__device__ float g_Vt[(size_t)BZ * NH * DH * LQ];          // 16 MB (V transposed: [bh][dh][Lq])
__device__ float g_norm[BZ * LQ];
__device__ unsigned char g_mask[(size_t)BZ * LQ * LQ];     // 8 MB (1 = masked)
__device__ float g_S[(size_t)BZ * NH * LQ * LQ];           // 256 MB scores/probs

__device__ __forceinline__ float tf32r(float x) {
    float y;
    asm("cvt.rna.tf32.f32 %0, %1;" : "=f"(y) : "f"(x));
    return y;
}

#define MMA_TF32(c0, c1, c2, c3, a0, a1, a2, a3, b0, b1) \
    asm volatile("mma.sync.aligned.m16n8k8.row.col.f32.tf32.tf32.f32 " \
        "{%0,%1,%2,%3}, {%4,%5,%6,%7}, {%8,%9}, {%0,%1,%2,%3};" \
        : "+f"(c0), "+f"(c1), "+f"(c2), "+f"(c3) \
        : "r"(a0), "r"(a1), "r"(a2), "r"(a3), "r"(b0), "r"(b1))

// ---------------- reduction helpers ----------------------------------------
__device__ __forceinline__ float warp_max(float v) {
#pragma unroll
    for (int o = 16; o > 0; o >>= 1) v = fmaxf(v, __shfl_xor_sync(0xffffffffu, v, o));
    return v;
}
__device__ __forceinline__ float warp_sum(float v) {
#pragma unroll
    for (int o = 16; o > 0; o >>= 1) v += __shfl_xor_sync(0xffffffffu, v, o);
    return v;
}

// ==================== tf32 mma.sync GEMM core ===============================
// C[128, NT] = A[128, K] @ B[NT, K]^T, A/B K-major (row strides in floats).
// Block 256 threads = 8 warps (2 x 4); warp tile 64 x (NT/4).
// NFRAG = NT/32 (n8-fragments per warp).
template <int NFRAG>
__device__ __forceinline__ void mma_chunk(const float* __restrict__ As,
                                          const float* __restrict__ Bs,
                                          int wm, int wn, int lane,
                                          float (&acc)[4][NFRAG][4]) {
    const int rr = lane >> 2, cc = lane & 3;
#pragma unroll
    for (int ks = 0; ks < 4; ks++) {
        const int kk = ks * 8;
        uint32_t a[4][4];
#pragma unroll
        for (int mf = 0; mf < 4; mf++) {
            const float* p = As + (wm * 64 + mf * 16 + rr) * SSTR + kk + cc;
            a[mf][0] = __float_as_uint(p[0]);
            a[mf][1] = __float_as_uint(p[8 * SSTR]);
            a[mf][2] = __float_as_uint(p[4]);
            a[mf][3] = __float_as_uint(p[8 * SSTR + 4]);
        }
#pragma unroll
        for (int nf = 0; nf < NFRAG; nf++) {
            const float* pb = Bs + (wn * (NFRAG * 8) + nf * 8 + rr) * SSTR + kk + cc;
            uint32_t b0 = __float_as_uint(pb[0]);
            uint32_t b1 = __float_as_uint(pb[4]);
#pragma unroll
            for (int mf = 0; mf < 4; mf++)
                MMA_TF32(acc[mf][nf][0], acc[mf][nf][1], acc[mf][nf][2], acc[mf][nf][3],
                         a[mf][0], a[mf][1], a[mf][2], a[mf][3], b0, b1);
        }
    }
}

template <int NCH, int NT>
__device__ __forceinline__ void gemm_mma(const float* __restrict__ Ab, int Astr,
                                         const float* __restrict__ Bb, int Bstr,
                                         float* As, float* Bs,
                                         float (&acc)[4][NT / 32][4]) {
    const int tid = threadIdx.x;
    const int w = tid >> 5, lane = tid & 31;
    const int wm = w & 1, wn = w >> 1;
    for (int it = 0; it < NCH; ++it) {
        if (it) __syncthreads();
#pragma unroll
        for (int i = 0; i < 4; i++) {                   // A: 128 rows x 32 cols
            int idx = tid + i * 256;
            int r = idx >> 3, c4 = idx & 7;
            float4 v = *(const float4*)(Ab + (size_t)r * Astr + it * 32 + c4 * 4);
            v.x = tf32r(v.x); v.y = tf32r(v.y); v.z = tf32r(v.z); v.w = tf32r(v.w);
            *(float4*)&As[r * SSTR + c4 * 4] = v;
        }
#pragma unroll
        for (int i = 0; i < NT / 32; i++) {             // B: NT rows x 32 cols
            int idx = tid + i * 256;
            int r = idx >> 3, c4 = idx & 7;
            float4 v = *(const float4*)(Bb + (size_t)r * Bstr + it * 32 + c4 * 4);
            v.x = tf32r(v.x); v.y = tf32r(v.y); v.z = tf32r(v.z); v.w = tf32r(v.w);
            *(float4*)&Bs[r * SSTR + c4 * 4] = v;
        }
        __syncthreads();
        mma_chunk<NT / 32>(As, Bs, wm, wn, lane, acc);
    }
}

// ---------------- row norms of h (fp32 exact) -------------------------------
__global__ void norm_kernel(const float* __restrict__ q) {
    int row = blockIdx.x;              // b*LQ + l
    int b = row / LQ, l = row % LQ;
    const float* h = q + ((size_t)l * BZ + b) * D;
    float s = 0.f;
    for (int k = threadIdx.x; k < D; k += 128) {
        float v = h[k];
        s = fmaf(v, v, s);
    }
    __shared__ float red[4];
    s = warp_sum(s);
    int wid = threadIdx.x >> 5, lane = threadIdx.x & 31;
    if (lane == 0) red[wid] = s;
    __syncthreads();
    if (threadIdx.x == 0)
        g_norm[row] = fmaxf(sqrtf(red[0] + red[1] + red[2] + red[3]), 1e-8f);
}

// ---------------- projections ------------------------------------------------
// grid (4 n-tiles, 64 = b*8+mtile, 3 which)
__global__ __launch_bounds__(256) void proj_kernel(
    const float* __restrict__ q,
    const float* __restrict__ Wq, const float* __restrict__ Wk, const float* __restrict__ Wv,
    const float* __restrict__ bq, const float* __restrict__ bk, const float* __restrict__ bv) {
    __shared__ float As[128 * SSTR];
    __shared__ float Bs[128 * SSTR];
    const int tid = threadIdx.x;
    const int which = blockIdx.z;
    const int b = blockIdx.y >> 3;
    const int i0 = (blockIdx.y & 7) * 128;
    const int col0 = blockIdx.x * 128;
    const float* W = (which == 0) ? Wq : (which == 1) ? Wk : Wv;
    const float* bias = (which == 0) ? bq : (which == 1) ? bk : bv;

    float acc[4][4][4] = {};
    const float* Ab = q + (size_t)i0 * (BZ * D) + (size_t)b * D;   // stride BZ*D
    const float* Bb = W + (size_t)col0 * D;                        // stride D
    gemm_mma<D / 32, 128>(Ab, BZ * D, Bb, D, As, Bs, acc);

    const int w = tid >> 5, lane = tid & 31;
    const int wm = w & 1, wn = w >> 1;
    const int rbase = wm * 64 + (lane >> 2);
    const int cbase = wn * 32 + (lane & 3) * 2;
    if (which < 2) {
        float* out = (which == 0) ? g_Q : g_K;
#pragma unroll
        for (int mf = 0; mf < 4; mf++) {
            int r0 = i0 + rbase + mf * 16;
#pragma unroll
            for (int nf = 0; nf < 4; nf++) {
                int c = col0 + cbase + nf * 8;
                float2 bb = *(const float2*)&bias[c];
                float2 v0 = make_float2(acc[mf][nf][0] + bb.x, acc[mf][nf][1] + bb.y);
                float2 v1 = make_float2(acc[mf][nf][2] + bb.x, acc[mf][nf][3] + bb.y);
                *(float2*)&out[((size_t)(b * LQ + r0)) * D + c] = v0;
                *(float2*)&out[((size_t)(b * LQ + r0 + 8)) * D + c] = v1;
            }
        }
    } else {   // V -> transposed: g_Vt[((b*NH + h)*DH + dh)*LQ + i]
#pragma unroll
        for (int mf = 0; mf < 4; mf++) {
            int r0 = i0 + rbase + mf * 16;
#pragma unroll
            for (int nf = 0; nf < 4; nf++) {
                int n = col0 + cbase + nf * 8;
                float2 bb = *(const float2*)&bias[n];
                size_t o0 = ((size_t)(b * NH + (n >> 6)) * DH + (n & 63)) * LQ;
                size_t o1 = ((size_t)(b * NH + ((n + 1) >> 6)) * DH + ((n + 1) & 63)) * LQ;
                g_Vt[o0 + r0]     = acc[mf][nf][0] + bb.x;
                g_Vt[o1 + r0]     = acc[mf][nf][1] + bb.y;
                g_Vt[o0 + r0 + 8] = acc[mf][nf][2] + bb.x;
                g_Vt[o1 + r0 + 8] = acc[mf][nf][3] + bb.y;
            }
        }
    }
}

// ---------------- cosine GEMM + IoU mask ------------------------------------
// grid (8 j-tiles, 8 i-tiles, 8 b)
__global__ __launch_bounds__(256) void mask_kernel(const float* __restrict__ q,
                                                   const float* __restrict__ seg) {
    __shared__ float As[128 * SSTR];
    __shared__ float Bs[128 * SSTR];
    const int tid = threadIdx.x;
    const int b = blockIdx.z;
    const int i0 = blockIdx.y * 128;
    const int j0 = blockIdx.x * 128;

    float acc[4][4][4] = {};
    const float* Ab = q + (size_t)i0 * (BZ * D) + (size_t)b * D;
    const float* Bb = q + (size_t)j0 * (BZ * D) + (size_t)b * D;
    gemm_mma<D / 32, 128>(Ab, BZ * D, Bb, BZ * D, As, Bs, acc);

    // aux tables in As (all warps finished reading after sync)
    __syncthreads();
    float4* auxr = (float4*)As;            // [128]: rn, rs, re, rl
    float4* auxc = (float4*)(As + 512);    // [128]: cn, cs, ce, cl
    if (tid < 128) {
        int r = i0 + tid;
        float2 sg = *(const float2*)(seg + ((size_t)b * LQ + r) * 2);
        auxr[tid] = make_float4(g_norm[b * LQ + r], sg.x - 0.5f * sg.y,
                                sg.x + 0.5f * sg.y, sg.y);
    } else {
        int t = tid - 128;
        int c = j0 + t;
        float2 sg = *(const float2*)(seg + ((size_t)b * LQ + c) * 2);
        auxc[t] = make_float4(g_norm[b * LQ + c], sg.x - 0.5f * sg.y,
                              sg.x + 0.5f * sg.y, sg.y);
    }
    __syncthreads();

    const int w = tid >> 5, lane = tid & 31;
    const int wm = w & 1, wn = w >> 1;
    const int rbase = wm * 64 + (lane >> 2);
    const int cbase = wn * 32 + (lane & 3) * 2;
#pragma unroll
    for (int mf = 0; mf < 4; mf++) {
#pragma unroll
        for (int half = 0; half < 2; half++) {
            int rl_ = rbase + mf * 16 + half * 8;   // local row
            float4 ar = auxr[rl_];
            int rg = i0 + rl_;
#pragma unroll
            for (int nf = 0; nf < 4; nf++) {
                int cl_ = cbase + nf * 8;
                uchar2 mm;
#pragma unroll
                for (int e = 0; e < 2; e++) {
                    float4 ac = auxc[cl_ + e];
                    float cosv = acc[mf][nf][half * 2 + e] / (ar.x * ac.x);
                    float inter = fmaxf(fminf(ar.z, ac.z) - fmaxf(ar.y, ac.y), 0.f);
                    float iou = inter / (ar.w + ac.w - inter);
                    int cg = j0 + cl_ + e;
                    bool adj = (cosv > COS_THR) && ((iou <= IOU_THR) || (rg == cg));
                    if (e == 0) mm.x = adj ? 0 : 1; else mm.y = adj ? 0 : 1;
                }
                *(uchar2*)&g_mask[((size_t)(b * LQ + rg)) * LQ + j0 + cl_] = mm;
            }
        }
    }
}

// ---------------- scores: S = QK^T/8 with mask -> -inf ----------------------
// grid (8 j-tiles, 8 i-tiles, 64 bh)
__global__ __launch_bounds__(256) void scores_kernel() {
    __shared__ float As[128 * SSTR];
    __shared__ float Bs[128 * SSTR];
    const int tid = threadIdx.x;
    const int bh = blockIdx.z;
    const int b = bh >> 3, h = bh & 7;
    const int i0 = blockIdx.y * 128;
    const int j0 = blockIdx.x * 128;

    float acc[4][4][4] = {};
    const float* Ab = g_Q + ((size_t)(b * LQ + i0)) * D + h * DH;
    const float* Bb = g_K + ((size_t)(b * LQ + j0)) * D + h * DH;
    gemm_mma<DH / 32, 128>(Ab, D, Bb, D, As, Bs, acc);

    const int w = tid >> 5, lane = tid & 31;
    const int wm = w & 1, wn = w >> 1;
    const int rbase = wm * 64 + (lane >> 2);
    const int cbase = wn * 32 + (lane & 3) * 2;
    const float NEG_INF = __int_as_float(0xff800000);
#pragma unroll
    for (int mf = 0; mf < 4; mf++) {
#pragma unroll
        for (int half = 0; half < 2; half++) {
            int r = i0 + rbase + mf * 16 + half * 8;
            const unsigned char* mrow = g_mask + ((size_t)(b * LQ + r)) * LQ + j0;
            float* srow = g_S + ((size_t)bh * LQ + r) * LQ + j0;
#pragma unroll
            for (int nf = 0; nf < 4; nf++) {
                int c = cbase + nf * 8;
                uchar2 mm = *(const uchar2*)&mrow[c];
                float2 v;
                v.x = mm.x ? NEG_INF : acc[mf][nf][half * 2 + 0] * 0.125f;
                v.y = mm.y ? NEG_INF : acc[mf][nf][half * 2 + 1] * 0.125f;
                *(float2*)&srow[c] = v;
            }
        }
    }
}

// ---------------- row softmax over g_S --------------------------------------
__global__ void softmax_kernel() {
    const size_t row = blockIdx.x;
    float* S = g_S + row * LQ;
    const int tid = threadIdx.x;       // 256 threads
    float v[4];
    float m = __int_as_float(0xff800000);
#pragma unroll
    for (int i = 0; i < 4; i++) {
        v[i] = S[tid + (i << 8)];
        m = fmaxf(m, v[i]);
    }
    __shared__ float redm[8];
    __shared__ float reds[8];
    m = warp_max(m);
    if (!(tid & 31)) redm[tid >> 5] = m;
    __syncthreads();
    float m2 = redm[0];
#pragma unroll
    for (int i = 1; i < 8; i++) m2 = fmaxf(m2, redm[i]);
    float s = 0.f;
#pragma unroll
    for (int i = 0; i < 4; i++) {
        v[i] = __expf(v[i] - m2);
        s += v[i];
    }
    s = warp_sum(s);
    if (!(tid & 31)) reds[tid >> 5] = s;
    __syncthreads();
    float tot = reds[0];
#pragma unroll
    for (int i = 1; i < 8; i++) tot += reds[i];
    float inv = 1.0f / tot;
#pragma unroll
    for (int i = 0; i < 4; i++) S[tid + (i << 8)] = v[i] * inv;
}

// ---------------- O = P @ V_h^T + residual ----------------------------------
// grid (8 i-tiles, 64 bh); NT=64
__global__ __launch_bounds__(256) void attnv_kernel(const float* __restrict__ q,
                                                    float* __restrict__ out) {
    __shared__ float As[128 * SSTR];
    __shared__ float Bs[64 * SSTR];
    const int tid = threadIdx.x;
    const int bh = blockIdx.y;
    const int b = bh >> 3, h = bh & 7;
    const int i0 = blockIdx.x * 128;

    float acc[4][2][4] = {};
    const float* Ab = g_S + ((size_t)bh * LQ + i0) * LQ;       // stride LQ
    const float* Bb = g_Vt + (size_t)bh * DH * LQ;             // stride LQ
    gemm_mma<LQ / 32, 64>(Ab, LQ, Bb, LQ, As, Bs, acc);

    const int w = tid >> 5, lane = tid & 31;
    const int wm = w & 1, wn = w >> 1;
    const int rbase = wm * 64 + (lane >> 2);
    const int cbase = wn * 16 + (lane & 3) * 2;
#pragma unroll
    for (int mf = 0; mf < 4; mf++) {
#pragma unroll
        for (int half = 0; half < 2; half++) {
            int r = i0 + rbase + mf * 16 + half * 8;
#pragma unroll
            for (int nf = 0; nf < 2; nf++) {
                int c = cbase + nf * 8;
                size_t o = ((size_t)r * BZ + b) * D + h * DH + c;
                float2 qv = *(const float2*)(q + o);
                float2 v = make_float2(qv.x + acc[mf][nf][half * 2 + 0],
                                       qv.y + acc[mf][nf][half * 2 + 1]);
                *(float2*)&out[o] = v;
            }
        }
    }
}

// ---------------- launch ----------------------------------------------------
extern "C" void kernel_launch(void* const* d_in, const int* in_sizes, int n_in,
                              void* d_out, int out_size) {
    const float* query = (const float*)d_in[0];
    const float* seg   = (const float*)d_in[1];
    const float* Wq    = (const float*)d_in[2];
    const float* bq    = (const float*)d_in[3];
    const float* Wk    = (const float*)d_in[4];
    const float* bk    = (const float*)d_in[5];
    const float* Wv    = (const float*)d_in[6];
    const float* bv    = (const float*)d_in[7];
    float* out = (float*)d_out;

    norm_kernel<<<BZ * LQ, 128>>>(query);
    proj_kernel<<<dim3(4, 64, 3), 256>>>(query, Wq, Wk, Wv, bq, bk, bv);
    mask_kernel<<<dim3(8, 8, 8), 256>>>(query, seg);
    scores_kernel<<<dim3(8, 8, 64), 256>>>();
    softmax_kernel<<<BZ * NH * LQ, 256>>>();
    attnv_kernel<<<dim3(8, 64), 256>>>(query, out);
}

// round 5
// speedup vs baseline: 3.1374x; 1.4721x over previous
#include <cuda_runtime.h>
#include <math.h>
#include <stdint.h>

#define LQ 1024
#define BZ 8
#define D  512
#define NH 8
#define DH 64
#define IOU_THR 0.2f
#define COS_THR 0.2f
#define NEGF -3.402823466e38f

#define SSTR 36   // smem row stride (floats) for 32-col tiles
#define FSTR 68   // smem row stride (floats) for 64-col tiles (flash kernel)

// ---------------- scratch (static device globals; no allocations) ----------
__device__ float g_Q[(size_t)BZ * LQ * D];                 // 16 MB
__device__ float g_K[(size_t)BZ * LQ * D];                 // 16 MB
__device__ float g_Vt[(size_t)BZ * NH * DH * LQ];          // 16 MB ([bh][dh][Lq])
__device__ float g_norm[BZ * LQ];
__device__ unsigned char g_mask[(size_t)BZ * LQ * LQ];     // 8 MB (1 = masked)

__device__ __forceinline__ float tf32r(float x) {
    float y;
    asm("cvt.rna.tf32.f32 %0, %1;" : "=f"(y) : "f"(x));
    return y;
}

#define MMA_TF32(c0, c1, c2, c3, a0, a1, a2, a3, b0, b1) \
    asm volatile("mma.sync.aligned.m16n8k8.row.col.f32.tf32.tf32.f32 " \
        "{%0,%1,%2,%3}, {%4,%5,%6,%7}, {%8,%9}, {%0,%1,%2,%3};" \
        : "+f"(c0), "+f"(c1), "+f"(c2), "+f"(c3) \
        : "r"(a0), "r"(a1), "r"(a2), "r"(a3), "r"(b0), "r"(b1))

// ---------------- reduction helpers ----------------------------------------
__device__ __forceinline__ float warp_sum(float v) {
#pragma unroll
    for (int o = 16; o > 0; o >>= 1) v += __shfl_xor_sync(0xffffffffu, v, o);
    return v;
}

// ==================== tf32 mma.sync GEMM core (proj / mask) =================
template <int NFRAG>
__device__ __forceinline__ void mma_chunk(const float* __restrict__ As,
                                          const float* __restrict__ Bs,
                                          int wm, int wn, int lane,
                                          float (&acc)[4][NFRAG][4]) {
    const int rr = lane >> 2, cc = lane & 3;
#pragma unroll
    for (int ks = 0; ks < 4; ks++) {
        const int kk = ks * 8;
        uint32_t a[4][4];
#pragma unroll
        for (int mf = 0; mf < 4; mf++) {
            const float* p = As + (wm * 64 + mf * 16 + rr) * SSTR + kk + cc;
            a[mf][0] = __float_as_uint(p[0]);
            a[mf][1] = __float_as_uint(p[8 * SSTR]);
            a[mf][2] = __float_as_uint(p[4]);
            a[mf][3] = __float_as_uint(p[8 * SSTR + 4]);
        }
#pragma unroll
        for (int nf = 0; nf < NFRAG; nf++) {
            const float* pb = Bs + (wn * (NFRAG * 8) + nf * 8 + rr) * SSTR + kk + cc;
            uint32_t b0 = __float_as_uint(pb[0]);
            uint32_t b1 = __float_as_uint(pb[4]);
#pragma unroll
            for (int mf = 0; mf < 4; mf++)
                MMA_TF32(acc[mf][nf][0], acc[mf][nf][1], acc[mf][nf][2], acc[mf][nf][3],
                         a[mf][0], a[mf][1], a[mf][2], a[mf][3], b0, b1);
        }
    }
}

template <int NCH, int NT>
__device__ __forceinline__ void gemm_mma(const float* __restrict__ Ab, int Astr,
                                         const float* __restrict__ Bb, int Bstr,
                                         float* As, float* Bs,
                                         float (&acc)[4][NT / 32][4]) {
    const int tid = threadIdx.x;
    const int w = tid >> 5, lane = tid & 31;
    const int wm = w & 1, wn = w >> 1;
    for (int it = 0; it < NCH; ++it) {
        if (it) __syncthreads();
#pragma unroll
        for (int i = 0; i < 4; i++) {
            int idx = tid + i * 256;
            int r = idx >> 3, c4 = idx & 7;
            float4 v = *(const float4*)(Ab + (size_t)r * Astr + it * 32 + c4 * 4);
            v.x = tf32r(v.x); v.y = tf32r(v.y); v.z = tf32r(v.z); v.w = tf32r(v.w);
            *(float4*)&As[r * SSTR + c4 * 4] = v;
        }
#pragma unroll
        for (int i = 0; i < NT / 32; i++) {
            int idx = tid + i * 256;
            int r = idx >> 3, c4 = idx & 7;
            float4 v = *(const float4*)(Bb + (size_t)r * Bstr + it * 32 + c4 * 4);
            v.x = tf32r(v.x); v.y = tf32r(v.y); v.z = tf32r(v.z); v.w = tf32r(v.w);
            *(float4*)&Bs[r * SSTR + c4 * 4] = v;
        }
        __syncthreads();
        mma_chunk<NT / 32>(As, Bs, wm, wn, lane, acc);
    }
}

// ---------------- row norms of h (fp32 exact) -------------------------------
__global__ void norm_kernel(const float* __restrict__ q) {
    int row = blockIdx.x;              // b*LQ + l
    int b = row / LQ, l = row % LQ;
    const float* h = q + ((size_t)l * BZ + b) * D;
    float s = 0.f;
    for (int k = threadIdx.x; k < D; k += 128) {
        float v = h[k];
        s = fmaf(v, v, s);
    }
    __shared__ float red[4];
    s = warp_sum(s);
    int wid = threadIdx.x >> 5, lane = threadIdx.x & 31;
    if (lane == 0) red[wid] = s;
    __syncthreads();
    if (threadIdx.x == 0)
        g_norm[row] = fmaxf(sqrtf(red[0] + red[1] + red[2] + red[3]), 1e-8f);
}

// ---------------- projections ------------------------------------------------
__global__ __launch_bounds__(256) void proj_kernel(
    const float* __restrict__ q,
    const float* __restrict__ Wq, const float* __restrict__ Wk, const float* __restrict__ Wv,
    const float* __restrict__ bq, const float* __restrict__ bk, const float* __restrict__ bv) {
    __shared__ float As[128 * SSTR];
    __shared__ float Bs[128 * SSTR];
    const int tid = threadIdx.x;
    const int which = blockIdx.z;
    const int b = blockIdx.y >> 3;
    const int i0 = (blockIdx.y & 7) * 128;
    const int col0 = blockIdx.x * 128;
    const float* W = (which == 0) ? Wq : (which == 1) ? Wk : Wv;
    const float* bias = (which == 0) ? bq : (which == 1) ? bk : bv;

    float acc[4][4][4] = {};
    const float* Ab = q + (size_t)i0 * (BZ * D) + (size_t)b * D;
    const float* Bb = W + (size_t)col0 * D;
    gemm_mma<D / 32, 128>(Ab, BZ * D, Bb, D, As, Bs, acc);

    const int w = tid >> 5, lane = tid & 31;
    const int wm = w & 1, wn = w >> 1;
    const int rbase = wm * 64 + (lane >> 2);
    const int cbase = wn * 32 + (lane & 3) * 2;
    if (which < 2) {
        float* out = (which == 0) ? g_Q : g_K;
#pragma unroll
        for (int mf = 0; mf < 4; mf++) {
            int r0 = i0 + rbase + mf * 16;
#pragma unroll
            for (int nf = 0; nf < 4; nf++) {
                int c = col0 + cbase + nf * 8;
                float2 bb = *(const float2*)&bias[c];
                float2 v0 = make_float2(acc[mf][nf][0] + bb.x, acc[mf][nf][1] + bb.y);
                float2 v1 = make_float2(acc[mf][nf][2] + bb.x, acc[mf][nf][3] + bb.y);
                *(float2*)&out[((size_t)(b * LQ + r0)) * D + c] = v0;
                *(float2*)&out[((size_t)(b * LQ + r0 + 8)) * D + c] = v1;
            }
        }
    } else {   // V -> transposed: g_Vt[((b*NH + h)*DH + dh)*LQ + i]
#pragma unroll
        for (int mf = 0; mf < 4; mf++) {
            int r0 = i0 + rbase + mf * 16;
#pragma unroll
            for (int nf = 0; nf < 4; nf++) {
                int n = col0 + cbase + nf * 8;
                float2 bb = *(const float2*)&bias[n];
                size_t o0 = ((size_t)(b * NH + (n >> 6)) * DH + (n & 63)) * LQ;
                size_t o1 = ((size_t)(b * NH + ((n + 1) >> 6)) * DH + ((n + 1) & 63)) * LQ;
                g_Vt[o0 + r0]     = acc[mf][nf][0] + bb.x;
                g_Vt[o1 + r0]     = acc[mf][nf][1] + bb.y;
                g_Vt[o0 + r0 + 8] = acc[mf][nf][2] + bb.x;
                g_Vt[o1 + r0 + 8] = acc[mf][nf][3] + bb.y;
            }
        }
    }
}

// ---------------- cosine GEMM + IoU mask ------------------------------------
__global__ __launch_bounds__(256) void mask_kernel(const float* __restrict__ q,
                                                   const float* __restrict__ seg) {
    __shared__ float As[128 * SSTR];
    __shared__ float Bs[128 * SSTR];
    const int tid = threadIdx.x;
    const int b = blockIdx.z;
    const int i0 = blockIdx.y * 128;
    const int j0 = blockIdx.x * 128;

    float acc[4][4][4] = {};
    const float* Ab = q + (size_t)i0 * (BZ * D) + (size_t)b * D;
    const float* Bb = q + (size_t)j0 * (BZ * D) + (size_t)b * D;
    gemm_mma<D / 32, 128>(Ab, BZ * D, Bb, BZ * D, As, Bs, acc);

    __syncthreads();
    float4* auxr = (float4*)As;            // [128]: rn, rs, re, rl
    float4* auxc = (float4*)(As + 512);    // [128]: cn, cs, ce, cl
    if (tid < 128) {
        int r = i0 + tid;
        float2 sg = *(const float2*)(seg + ((size_t)b * LQ + r) * 2);
        auxr[tid] = make_float4(g_norm[b * LQ + r], sg.x - 0.5f * sg.y,
                                sg.x + 0.5f * sg.y, sg.y);
    } else {
        int t = tid - 128;
        int c = j0 + t;
        float2 sg = *(const float2*)(seg + ((size_t)b * LQ + c) * 2);
        auxc[t] = make_float4(g_norm[b * LQ + c], sg.x - 0.5f * sg.y,
                              sg.x + 0.5f * sg.y, sg.y);
    }
    __syncthreads();

    const int w = tid >> 5, lane = tid & 31;
    const int wm = w & 1, wn = w >> 1;
    const int rbase = wm * 64 + (lane >> 2);
    const int cbase = wn * 32 + (lane & 3) * 2;
#pragma unroll
    for (int mf = 0; mf < 4; mf++) {
#pragma unroll
        for (int half = 0; half < 2; half++) {
            int rl_ = rbase + mf * 16 + half * 8;
            float4 ar = auxr[rl_];
            int rg = i0 + rl_;
#pragma unroll
            for (int nf = 0; nf < 4; nf++) {
                int cl_ = cbase + nf * 8;
                uchar2 mm;
#pragma unroll
                for (int e = 0; e < 2; e++) {
                    float4 ac = auxc[cl_ + e];
                    float cosv = acc[mf][nf][half * 2 + e] / (ar.x * ac.x);
                    float inter = fmaxf(fminf(ar.z, ac.z) - fmaxf(ar.y, ac.y), 0.f);
                    float iou = inter / (ar.w + ac.w - inter);
                    int cg = j0 + cl_ + e;
                    bool adj = (cosv > COS_THR) && ((iou <= IOU_THR) || (rg == cg));
                    if (e == 0) mm.x = adj ? 0 : 1; else mm.y = adj ? 0 : 1;
                }
                *(uchar2*)&g_mask[((size_t)(b * LQ + rg)) * LQ + j0 + cl_] = mm;
            }
        }
    }
}

// ==================== fused attention (flash-style) =========================
// grid (8 i-tiles, 64 bh), 256 threads = 8 warps, warp owns 16 rows.
// smem: sQ[128][FSTR] | sK[64][FSTR] | sV[64][FSTR] | sP[128][FSTR]
#define FSM_BYTES ((128 + 64 + 64 + 128) * FSTR * 4)

__global__ __launch_bounds__(256, 2) void flash_kernel(const float* __restrict__ q,
                                                       float* __restrict__ out) {
    extern __shared__ float sm[];
    float* sQ = sm;
    float* sK = sQ + 128 * FSTR;
    float* sV = sK + 64 * FSTR;
    float* sP = sV + 64 * FSTR;

    const int tid = threadIdx.x;
    const int w = tid >> 5, lane = tid & 31;
    const int rr = lane >> 2, cc = lane & 3;
    const int bh = blockIdx.y, b = bh >> 3, h = bh & 7;
    const int i0 = blockIdx.x * 128;
    const int wbase = w * 16;

    // persistent Q tile (tf32-rounded)
#pragma unroll
    for (int i = 0; i < 8; i++) {
        int idx = tid + i * 256;
        int r = idx >> 4, c4 = idx & 15;
        float4 v = *(const float4*)&g_Q[((size_t)(b * LQ + i0 + r)) * D + h * DH + c4 * 4];
        v.x = tf32r(v.x); v.y = tf32r(v.y); v.z = tf32r(v.z); v.w = tf32r(v.w);
        *(float4*)&sQ[r * FSTR + c4 * 4] = v;
    }

    float Oacc[8][4] = {};
    float m0 = NEGF, m1 = NEGF, l0 = 0.f, l1 = 0.f;
    const int r0g = i0 + wbase + rr, r1g = r0g + 8;
    const unsigned char* mrow0 = g_mask + ((size_t)(b * LQ + r0g)) * LQ;
    const unsigned char* mrow1 = g_mask + ((size_t)(b * LQ + r1g)) * LQ;

    for (int j0 = 0; j0 < LQ; j0 += 64) {
        __syncthreads();
#pragma unroll
        for (int i = 0; i < 4; i++) {           // K tile 64x64 + V tile 64x64
            int idx = tid + i * 256;
            int r = idx >> 4, c4 = idx & 15;
            float4 v = *(const float4*)&g_K[((size_t)(b * LQ + j0 + r)) * D + h * DH + c4 * 4];
            v.x = tf32r(v.x); v.y = tf32r(v.y); v.z = tf32r(v.z); v.w = tf32r(v.w);
            *(float4*)&sK[r * FSTR + c4 * 4] = v;
            float4 u = *(const float4*)&g_Vt[((size_t)bh * DH + r) * LQ + j0 + c4 * 4];
            u.x = tf32r(u.x); u.y = tf32r(u.y); u.z = tf32r(u.z); u.w = tf32r(u.w);
            *(float4*)&sV[r * FSTR + c4 * 4] = u;
        }
        __syncthreads();

        // S = Q K^T  (warp: 16 x 64)
        float Sacc[8][4] = {};
#pragma unroll
        for (int ks = 0; ks < 8; ks++) {
            const int kk = ks * 8;
            const float* pa = sQ + (wbase + rr) * FSTR + kk + cc;
            uint32_t a0 = __float_as_uint(pa[0]);
            uint32_t a1 = __float_as_uint(pa[8 * FSTR]);
            uint32_t a2 = __float_as_uint(pa[4]);
            uint32_t a3 = __float_as_uint(pa[8 * FSTR + 4]);
#pragma unroll
            for (int nf = 0; nf < 8; nf++) {
                const float* pb = sK + (nf * 8 + rr) * FSTR + kk + cc;
                uint32_t b0 = __float_as_uint(pb[0]);
                uint32_t b1 = __float_as_uint(pb[4]);
                MMA_TF32(Sacc[nf][0], Sacc[nf][1], Sacc[nf][2], Sacc[nf][3],
                         a0, a1, a2, a3, b0, b1);
            }
        }

        // scale + mask + tile row max
        float mx0 = NEGF, mx1 = NEGF;
#pragma unroll
        for (int nf = 0; nf < 8; nf++) {
            int c = j0 + nf * 8 + cc * 2;
            uchar2 ma = *(const uchar2*)&mrow0[c];
            uchar2 mb = *(const uchar2*)&mrow1[c];
            Sacc[nf][0] = ma.x ? NEGF : Sacc[nf][0] * 0.125f;
            Sacc[nf][1] = ma.y ? NEGF : Sacc[nf][1] * 0.125f;
            Sacc[nf][2] = mb.x ? NEGF : Sacc[nf][2] * 0.125f;
            Sacc[nf][3] = mb.y ? NEGF : Sacc[nf][3] * 0.125f;
            mx0 = fmaxf(mx0, fmaxf(Sacc[nf][0], Sacc[nf][1]));
            mx1 = fmaxf(mx1, fmaxf(Sacc[nf][2], Sacc[nf][3]));
        }
        mx0 = fmaxf(mx0, __shfl_xor_sync(0xffffffffu, mx0, 1));
        mx0 = fmaxf(mx0, __shfl_xor_sync(0xffffffffu, mx0, 2));
        mx1 = fmaxf(mx1, __shfl_xor_sync(0xffffffffu, mx1, 1));
        mx1 = fmaxf(mx1, __shfl_xor_sync(0xffffffffu, mx1, 2));

        float nm0 = fmaxf(m0, mx0), nm1 = fmaxf(m1, mx1);
        float al0 = __expf(m0 - nm0), al1 = __expf(m1 - nm1);
        m0 = nm0; m1 = nm1;

        float rs0 = 0.f, rs1 = 0.f;
#pragma unroll
        for (int nf = 0; nf < 8; nf++) {
            float p00 = __expf(Sacc[nf][0] - nm0);
            float p01 = __expf(Sacc[nf][1] - nm0);
            float p10 = __expf(Sacc[nf][2] - nm1);
            float p11 = __expf(Sacc[nf][3] - nm1);
            rs0 += p00 + p01; rs1 += p10 + p11;
            *(float2*)&sP[(wbase + rr) * FSTR + nf * 8 + cc * 2] =
                make_float2(tf32r(p00), tf32r(p01));
            *(float2*)&sP[(wbase + rr + 8) * FSTR + nf * 8 + cc * 2] =
                make_float2(tf32r(p10), tf32r(p11));
            Oacc[nf][0] *= al0; Oacc[nf][1] *= al0;
            Oacc[nf][2] *= al1; Oacc[nf][3] *= al1;
        }
        rs0 += __shfl_xor_sync(0xffffffffu, rs0, 1);
        rs0 += __shfl_xor_sync(0xffffffffu, rs0, 2);
        rs1 += __shfl_xor_sync(0xffffffffu, rs1, 1);
        rs1 += __shfl_xor_sync(0xffffffffu, rs1, 2);
        l0 = l0 * al0 + rs0;
        l1 = l1 * al1 + rs1;
        __syncwarp();

        // O += P @ V   (warp rows only touch warp-private sP rows)
#pragma unroll
        for (int ks = 0; ks < 8; ks++) {
            const int kk = ks * 8;
            const float* pa = sP + (wbase + rr) * FSTR + kk + cc;
            uint32_t a0 = __float_as_uint(pa[0]);
            uint32_t a1 = __float_as_uint(pa[8 * FSTR]);
            uint32_t a2 = __float_as_uint(pa[4]);
            uint32_t a3 = __float_as_uint(pa[8 * FSTR + 4]);
#pragma unroll
            for (int nf = 0; nf < 8; nf++) {
                const float* pb = sV + (nf * 8 + rr) * FSTR + kk + cc;
                uint32_t b0 = __float_as_uint(pb[0]);
                uint32_t b1 = __float_as_uint(pb[4]);
                MMA_TF32(Oacc[nf][0], Oacc[nf][1], Oacc[nf][2], Oacc[nf][3],
                         a0, a1, a2, a3, b0, b1);
            }
        }
    }

    // epilogue: 1/l, residual, write [Lq, bz, d]
    float inv0 = 1.0f / l0, inv1 = 1.0f / l1;
#pragma unroll
    for (int nf = 0; nf < 8; nf++) {
        int c = h * DH + nf * 8 + cc * 2;
        size_t o0 = ((size_t)r0g * BZ + b) * D + c;
        size_t o1 = ((size_t)r1g * BZ + b) * D + c;
        float2 q0 = *(const float2*)&q[o0];
        float2 q1 = *(const float2*)&q[o1];
        *(float2*)&out[o0] = make_float2(q0.x + Oacc[nf][0] * inv0,
                                         q0.y + Oacc[nf][1] * inv0);
        *(float2*)&out[o1] = make_float2(q1.x + Oacc[nf][2] * inv1,
                                         q1.y + Oacc[nf][3] * inv1);
    }
}

// ---------------- launch ----------------------------------------------------
extern "C" void kernel_launch(void* const* d_in, const int* in_sizes, int n_in,
                              void* d_out, int out_size) {
    const float* query = (const float*)d_in[0];
    const float* seg   = (const float*)d_in[1];
    const float* Wq    = (const float*)d_in[2];
    const float* bq    = (const float*)d_in[3];
    const float* Wk    = (const float*)d_in[4];
    const float* bk    = (const float*)d_in[5];
    const float* Wv    = (const float*)d_in[6];
    const float* bv    = (const float*)d_in[7];
    float* out = (float*)d_out;

    cudaFuncSetAttribute(flash_kernel, cudaFuncAttributeMaxDynamicSharedMemorySize,
                         FSM_BYTES);

    norm_kernel<<<BZ * LQ, 128>>>(query);
    proj_kernel<<<dim3(4, 64, 3), 256>>>(query, Wq, Wk, Wv, bq, bk, bv);
    mask_kernel<<<dim3(8, 8, 8), 256>>>(query, seg);
    flash_kernel<<<dim3(8, 64), 256, FSM_BYTES>>>(query, out);
}

// round 6
// speedup vs baseline: 4.0170x; 1.2804x over previous
#include <cuda_runtime.h>
#include <math.h>
#include <stdint.h>

#define LQ 1024
#define BZ 8
#define D  512
#define NH 8
#define DH 64
#define IOU_THR 0.2f
#define COS_THR 0.2f
#define NEGF -3.402823466e38f

#define SSTR 36   // smem row stride (floats) for proj/mask tiles
#define FSTR 72   // flash smem row stride: (r*36) mod 32 = 4r -> LDS.64 conflict-free

// ---------------- scratch (static device globals; no allocations) ----------
// g_Q/g_K: column-PAIR-permuted within 8-col groups (u<4 -> 2u else 2u-7), tf32-rounded
__device__ float g_Q[(size_t)BZ * LQ * D];                 // 16 MB
__device__ float g_K[(size_t)BZ * LQ * D];                 // 16 MB
__device__ float g_Vt[(size_t)BZ * NH * DH * LQ];          // 16 MB ([bh][dh][Lq]), tf32-rounded
__device__ float g_norm[BZ * LQ];
__device__ unsigned char g_mask[(size_t)BZ * LQ * LQ];     // 8 MB (1 = masked)

__device__ __forceinline__ float tf32r(float x) {
    float y;
    asm("cvt.rna.tf32.f32 %0, %1;" : "=f"(y) : "f"(x));
    return y;
}

#define MMA_TF32(c0, c1, c2, c3, a0, a1, a2, a3, b0, b1) \
    asm volatile("mma.sync.aligned.m16n8k8.row.col.f32.tf32.tf32.f32 " \
        "{%0,%1,%2,%3}, {%4,%5,%6,%7}, {%8,%9}, {%0,%1,%2,%3};" \
        : "+f"(c0), "+f"(c1), "+f"(c2), "+f"(c3) \
        : "r"(a0), "r"(a1), "r"(a2), "r"(a3), "r"(b0), "r"(b1))

__device__ __forceinline__ float warp_sum(float v) {
#pragma unroll
    for (int o = 16; o > 0; o >>= 1) v += __shfl_xor_sync(0xffffffffu, v, o);
    return v;
}

// ==================== tf32 mma.sync GEMM core (proj / mask) =================
template <int NFRAG>
__device__ __forceinline__ void mma_chunk(const float* __restrict__ As,
                                          const float* __restrict__ Bs,
                                          int wm, int wn, int lane,
                                          float (&acc)[4][NFRAG][4]) {
    const int rr = lane >> 2, cc = lane & 3;
#pragma unroll
    for (int ks = 0; ks < 4; ks++) {
        const int kk = ks * 8;
        uint32_t a[4][4];
#pragma unroll
        for (int mf = 0; mf < 4; mf++) {
            const float* p = As + (wm * 64 + mf * 16 + rr) * SSTR + kk + cc;
            a[mf][0] = __float_as_uint(p[0]);
            a[mf][1] = __float_as_uint(p[8 * SSTR]);
            a[mf][2] = __float_as_uint(p[4]);
            a[mf][3] = __float_as_uint(p[8 * SSTR + 4]);
        }
#pragma unroll
        for (int nf = 0; nf < NFRAG; nf++) {
            const float* pb = Bs + (wn * (NFRAG * 8) + nf * 8 + rr) * SSTR + kk + cc;
            uint32_t b0 = __float_as_uint(pb[0]);
            uint32_t b1 = __float_as_uint(pb[4]);
#pragma unroll
            for (int mf = 0; mf < 4; mf++)
                MMA_TF32(acc[mf][nf][0], acc[mf][nf][1], acc[mf][nf][2], acc[mf][nf][3],
                         a[mf][0], a[mf][1], a[mf][2], a[mf][3], b0, b1);
        }
    }
}

template <int NCH, int NT>
__device__ __forceinline__ void gemm_mma(const float* __restrict__ Ab, int Astr,
                                         const float* __restrict__ Bb, int Bstr,
                                         float* As, float* Bs,
                                         float (&acc)[4][NT / 32][4]) {
    const int tid = threadIdx.x;
    const int w = tid >> 5, lane = tid & 31;
    const int wm = w & 1, wn = w >> 1;
    for (int it = 0; it < NCH; ++it) {
        if (it) __syncthreads();
#pragma unroll
        for (int i = 0; i < 4; i++) {
            int idx = tid + i * 256;
            int r = idx >> 3, c4 = idx & 7;
            float4 v = *(const float4*)(Ab + (size_t)r * Astr + it * 32 + c4 * 4);
            v.x = tf32r(v.x); v.y = tf32r(v.y); v.z = tf32r(v.z); v.w = tf32r(v.w);
            *(float4*)&As[r * SSTR + c4 * 4] = v;
        }
#pragma unroll
        for (int i = 0; i < NT / 32; i++) {
            int idx = tid + i * 256;
            int r = idx >> 3, c4 = idx & 7;
            float4 v = *(const float4*)(Bb + (size_t)r * Bstr + it * 32 + c4 * 4);
            v.x = tf32r(v.x); v.y = tf32r(v.y); v.z = tf32r(v.z); v.w = tf32r(v.w);
            *(float4*)&Bs[r * SSTR + c4 * 4] = v;
        }
        __syncthreads();
        mma_chunk<NT / 32>(As, Bs, wm, wn, lane, acc);
    }
}

// ---------------- row norms of h (fp32 exact) -------------------------------
__global__ void norm_kernel(const float* __restrict__ q) {
    int row = blockIdx.x;
    int b = row / LQ, l = row % LQ;
    const float* h = q + ((size_t)l * BZ + b) * D;
    float s = 0.f;
    for (int k = threadIdx.x; k < D; k += 128) {
        float v = h[k];
        s = fmaf(v, v, s);
    }
    __shared__ float red[4];
    s = warp_sum(s);
    int wid = threadIdx.x >> 5, lane = threadIdx.x & 31;
    if (lane == 0) red[wid] = s;
    __syncthreads();
    if (threadIdx.x == 0)
        g_norm[row] = fmaxf(sqrtf(red[0] + red[1] + red[2] + red[3]), 1e-8f);
}

// ================ fused proj (bid<768) + mask (bid>=768) ====================
__global__ __launch_bounds__(256, 2) void pm_kernel(
    const float* __restrict__ q, const float* __restrict__ seg,
    const float* __restrict__ Wq, const float* __restrict__ Wk, const float* __restrict__ Wv,
    const float* __restrict__ bq, const float* __restrict__ bk, const float* __restrict__ bv) {
    __shared__ float As[128 * SSTR];
    __shared__ float Bs[128 * SSTR];
    const int tid = threadIdx.x;
    const int w = tid >> 5, lane = tid & 31;
    const int wm = w & 1, wn = w >> 1;
    const int bid = blockIdx.x;

    if (bid < 768) {   // ---------------- projection path ----------------
        const int which = bid >> 8;
        const int rem = bid & 255;
        const int col0 = (rem & 3) * 128;
        const int y = rem >> 2;
        const int b = y >> 3;
        const int i0 = (y & 7) * 128;
        const float* W = (which == 0) ? Wq : (which == 1) ? Wk : Wv;
        const float* bias = (which == 0) ? bq : (which == 1) ? bk : bv;

        float acc[4][4][4] = {};
        const float* Ab = q + (size_t)i0 * (BZ * D) + (size_t)b * D;
        const float* Bb = W + (size_t)col0 * D;
        gemm_mma<D / 32, 128>(Ab, BZ * D, Bb, D, As, Bs, acc);

        const int rbase = wm * 64 + (lane >> 2);
        const int cbase = wn * 32 + (lane & 3) * 2;
        if (which < 2) {
            // store col-pair-permuted + tf32-rounded
            float* out = (which == 0) ? g_Q : g_K;
            const int u = (lane & 3) * 2;                    // 0,2,4,6
            const int pos0 = (u < 4) ? 2 * u : 2 * u - 7;    // perm of even col
#pragma unroll
            for (int mf = 0; mf < 4; mf++) {
                int r0 = i0 + rbase + mf * 16;
#pragma unroll
                for (int nf = 0; nf < 4; nf++) {
                    int c = col0 + cbase + nf * 8;            // actual even col
                    float2 bb = *(const float2*)&bias[c];
                    int cper = (c & ~7) + pos0;
                    float* p0 = &out[((size_t)(b * LQ + r0)) * D + cper];
                    float* p1 = &out[((size_t)(b * LQ + r0 + 8)) * D + cper];
                    p0[0] = tf32r(acc[mf][nf][0] + bb.x);
                    p0[2] = tf32r(acc[mf][nf][1] + bb.y);
                    p1[0] = tf32r(acc[mf][nf][2] + bb.x);
                    p1[2] = tf32r(acc[mf][nf][3] + bb.y);
                }
            }
        } else {   // V -> transposed natural layout, tf32-rounded
#pragma unroll
            for (int mf = 0; mf < 4; mf++) {
                int r0 = i0 + rbase + mf * 16;
#pragma unroll
                for (int nf = 0; nf < 4; nf++) {
                    int n = col0 + cbase + nf * 8;
                    float2 bb = *(const float2*)&bias[n];
                    size_t o0 = ((size_t)(b * NH + (n >> 6)) * DH + (n & 63)) * LQ;
                    size_t o1 = ((size_t)(b * NH + ((n + 1) >> 6)) * DH + ((n + 1) & 63)) * LQ;
                    g_Vt[o0 + r0]     = tf32r(acc[mf][nf][0] + bb.x);
                    g_Vt[o1 + r0]     = tf32r(acc[mf][nf][1] + bb.y);
                    g_Vt[o0 + r0 + 8] = tf32r(acc[mf][nf][2] + bb.x);
                    g_Vt[o1 + r0 + 8] = tf32r(acc[mf][nf][3] + bb.y);
                }
            }
        }
    } else {   // ---------------- mask path ----------------
        const int mb = bid - 768;
        const int j0 = (mb & 7) * 128;
        const int i0 = ((mb >> 3) & 7) * 128;
        const int b = mb >> 6;

        float acc[4][4][4] = {};
        const float* Ab = q + (size_t)i0 * (BZ * D) + (size_t)b * D;
        const float* Bb = q + (size_t)j0 * (BZ * D) + (size_t)b * D;
        gemm_mma<D / 32, 128>(Ab, BZ * D, Bb, BZ * D, As, Bs, acc);

        __syncthreads();
        float4* auxr = (float4*)As;
        float4* auxc = (float4*)(As + 512);
        if (tid < 128) {
            int r = i0 + tid;
            float2 sg = *(const float2*)(seg + ((size_t)b * LQ + r) * 2);
            auxr[tid] = make_float4(g_norm[b * LQ + r], sg.x - 0.5f * sg.y,
                                    sg.x + 0.5f * sg.y, sg.y);
        } else {
            int t = tid - 128;
            int c = j0 + t;
            float2 sg = *(const float2*)(seg + ((size_t)b * LQ + c) * 2);
            auxc[t] = make_float4(g_norm[b * LQ + c], sg.x - 0.5f * sg.y,
                                  sg.x + 0.5f * sg.y, sg.y);
        }
        __syncthreads();

        const int rbase = wm * 64 + (lane >> 2);
        const int cbase = wn * 32 + (lane & 3) * 2;
#pragma unroll
        for (int mf = 0; mf < 4; mf++) {
#pragma unroll
            for (int half = 0; half < 2; half++) {
                int rl_ = rbase + mf * 16 + half * 8;
                float4 ar = auxr[rl_];
                int rg = i0 + rl_;
#pragma unroll
                for (int nf = 0; nf < 4; nf++) {
                    int cl_ = cbase + nf * 8;
                    uchar2 mm;
#pragma unroll
                    for (int e = 0; e < 2; e++) {
                        float4 ac = auxc[cl_ + e];
                        float cosv = acc[mf][nf][half * 2 + e] / (ar.x * ac.x);
                        float inter = fmaxf(fminf(ar.z, ac.z) - fmaxf(ar.y, ac.y), 0.f);
                        float iou = inter / (ar.w + ac.w - inter);
                        int cg = j0 + cl_ + e;
                        bool adj = (cosv > COS_THR) && ((iou <= IOU_THR) || (rg == cg));
                        if (e == 0) mm.x = adj ? 0 : 1; else mm.y = adj ? 0 : 1;
                    }
                    *(uchar2*)&g_mask[((size_t)(b * LQ + rg)) * LQ + j0 + cl_] = mm;
                }
            }
        }
    }
}

// ==================== fused attention (flash-style, reg-resident P) =========
// grid (8 i-tiles, 64 bh), 256 threads = 8 warps, warp owns 16 rows.
// smem: sQ[128][FSTR] | sK[64][FSTR] | sV[64][FSTR]   (no sP!)
#define FSM_BYTES ((128 + 64 + 64) * FSTR * 4)

__global__ __launch_bounds__(256, 2) void flash_kernel(const float* __restrict__ q,
                                                       float* __restrict__ out) {
    extern __shared__ float sm[];
    float* sQ = sm;
    float* sK = sQ + 128 * FSTR;
    float* sV = sK + 64 * FSTR;

    const int tid = threadIdx.x;
    const int w = tid >> 5, lane = tid & 31;
    const int rr = lane >> 2, cc = lane & 3;
    const int bh = blockIdx.y, b = bh >> 3, h = bh & 7;
    const int i0 = blockIdx.x * 128;
    const int wbase = w * 16;

    // stage Q (already tf32-rounded + col-permuted in g_Q)
#pragma unroll
    for (int i = 0; i < 8; i++) {
        int idx = tid + i * 256;
        int r = idx >> 4, c4 = idx & 15;
        *(float4*)&sQ[r * FSTR + c4 * 4] =
            *(const float4*)&g_Q[((size_t)(b * LQ + i0 + r)) * D + h * DH + c4 * 4];
    }

    float Oacc[8][4] = {};
    float m0 = NEGF, m1 = NEGF, l0 = 0.f, l1 = 0.f;
    const int r0g = i0 + wbase + rr, r1g = r0g + 8;
    const unsigned char* mrow0 = g_mask + ((size_t)(b * LQ + r0g)) * LQ;
    const unsigned char* mrow1 = g_mask + ((size_t)(b * LQ + r1g)) * LQ;

    for (int j0 = 0; j0 < LQ; j0 += 64) {
        __syncthreads();
#pragma unroll
        for (int i = 0; i < 4; i++) {           // stage K, V (pre-rounded)
            int idx = tid + i * 256;
            int r = idx >> 4, c4 = idx & 15;
            *(float4*)&sK[r * FSTR + c4 * 4] =
                *(const float4*)&g_K[((size_t)(b * LQ + j0 + r)) * D + h * DH + c4 * 4];
            *(float4*)&sV[r * FSTR + c4 * 4] =
                *(const float4*)&g_Vt[((size_t)bh * DH + r) * LQ + j0 + c4 * 4];
        }
        __syncthreads();

        // S = Q K^T  — paired-column layout: every frag load is one LDS.64
        float Sacc[8][4] = {};
#pragma unroll
        for (int ks = 0; ks < 8; ks++) {
            const float* pa = sQ + (wbase + rr) * FSTR + ks * 8 + 2 * cc;
            float2 aA = *(const float2*)pa;               // a0 (col cc), a2 (col cc+4)
            float2 aB = *(const float2*)(pa + 8 * FSTR);  // a1, a3
            uint32_t a0 = __float_as_uint(aA.x), a2 = __float_as_uint(aA.y);
            uint32_t a1 = __float_as_uint(aB.x), a3 = __float_as_uint(aB.y);
#pragma unroll
            for (int nf = 0; nf < 8; nf++) {
                float2 bb = *(const float2*)(sK + (nf * 8 + rr) * FSTR + ks * 8 + 2 * cc);
                MMA_TF32(Sacc[nf][0], Sacc[nf][1], Sacc[nf][2], Sacc[nf][3],
                         a0, a1, a2, a3, __float_as_uint(bb.x), __float_as_uint(bb.y));
            }
        }

        // scale + mask + tile row max (C cols = 2cc, 2cc+1 — natural j)
        float mx0 = NEGF, mx1 = NEGF;
#pragma unroll
        for (int nf = 0; nf < 8; nf++) {
            int c = j0 + nf * 8 + cc * 2;
            uchar2 ma = *(const uchar2*)&mrow0[c];
            uchar2 mb = *(const uchar2*)&mrow1[c];
            Sacc[nf][0] = ma.x ? NEGF : Sacc[nf][0] * 0.125f;
            Sacc[nf][1] = ma.y ? NEGF : Sacc[nf][1] * 0.125f;
            Sacc[nf][2] = mb.x ? NEGF : Sacc[nf][2] * 0.125f;
            Sacc[nf][3] = mb.y ? NEGF : Sacc[nf][3] * 0.125f;
            mx0 = fmaxf(mx0, fmaxf(Sacc[nf][0], Sacc[nf][1]));
            mx1 = fmaxf(mx1, fmaxf(Sacc[nf][2], Sacc[nf][3]));
        }
        mx0 = fmaxf(mx0, __shfl_xor_sync(0xffffffffu, mx0, 1));
        mx0 = fmaxf(mx0, __shfl_xor_sync(0xffffffffu, mx0, 2));
        mx1 = fmaxf(mx1, __shfl_xor_sync(0xffffffffu, mx1, 1));
        mx1 = fmaxf(mx1, __shfl_xor_sync(0xffffffffu, mx1, 2));

        float nm0 = fmaxf(m0, mx0), nm1 = fmaxf(m1, mx1);
        float al0 = __expf(m0 - nm0), al1 = __expf(m1 - nm1);
        m0 = nm0; m1 = nm1;

        // exp in place (P stays in registers, tf32-rounded)
        float rs0 = 0.f, rs1 = 0.f;
#pragma unroll
        for (int nf = 0; nf < 8; nf++) {
            float p00 = __expf(Sacc[nf][0] - nm0);
            float p01 = __expf(Sacc[nf][1] - nm0);
            float p10 = __expf(Sacc[nf][2] - nm1);
            float p11 = __expf(Sacc[nf][3] - nm1);
            rs0 += p00 + p01; rs1 += p10 + p11;
            Sacc[nf][0] = tf32r(p00); Sacc[nf][1] = tf32r(p01);
            Sacc[nf][2] = tf32r(p10); Sacc[nf][3] = tf32r(p11);
            Oacc[nf][0] *= al0; Oacc[nf][1] *= al0;
            Oacc[nf][2] *= al1; Oacc[nf][3] *= al1;
        }
        rs0 += __shfl_xor_sync(0xffffffffu, rs0, 1);
        rs0 += __shfl_xor_sync(0xffffffffu, rs0, 2);
        rs1 += __shfl_xor_sync(0xffffffffu, rs1, 1);
        rs1 += __shfl_xor_sync(0xffffffffu, rs1, 2);
        l0 = l0 * al0 + rs0;
        l1 = l1 * al1 + rs1;

        // O += P @ V : A-frag = C-frag renamed {c0,c2,c1,c3};
        // A k-slot cc <-> P col 2cc, slot cc+4 <-> col 2cc+1, so V B-frag
        // rows (2cc, 2cc+1) are one natural-layout LDS.64.
#pragma unroll
        for (int ks = 0; ks < 8; ks++) {
            uint32_t a0 = __float_as_uint(Sacc[ks][0]);
            uint32_t a1 = __float_as_uint(Sacc[ks][2]);
            uint32_t a2 = __float_as_uint(Sacc[ks][1]);
            uint32_t a3 = __float_as_uint(Sacc[ks][3]);
#pragma unroll
            for (int nf = 0; nf < 8; nf++) {
                float2 bb = *(const float2*)(sV + (nf * 8 + rr) * FSTR + ks * 8 + 2 * cc);
                MMA_TF32(Oacc[nf][0], Oacc[nf][1], Oacc[nf][2], Oacc[nf][3],
                         a0, a1, a2, a3, __float_as_uint(bb.x), __float_as_uint(bb.y));
            }
        }
    }

    // epilogue: 1/l, residual, write [Lq, bz, d] (O cols = dh, natural)
    float inv0 = 1.0f / l0, inv1 = 1.0f / l1;
#pragma unroll
    for (int nf = 0; nf < 8; nf++) {
        int c = h * DH + nf * 8 + cc * 2;
        size_t o0 = ((size_t)r0g * BZ + b) * D + c;
        size_t o1 = ((size_t)r1g * BZ + b) * D + c;
        float2 q0 = *(const float2*)&q[o0];
        float2 q1 = *(const float2*)&q[o1];
        *(float2*)&out[o0] = make_float2(q0.x + Oacc[nf][0] * inv0,
                                         q0.y + Oacc[nf][1] * inv0);
        *(float2*)&out[o1] = make_float2(q1.x + Oacc[nf][2] * inv1,
                                         q1.y + Oacc[nf][3] * inv1);
    }
}

// ---------------- launch ----------------------------------------------------
extern "C" void kernel_launch(void* const* d_in, const int* in_sizes, int n_in,
                              void* d_out, int out_size) {
    const float* query = (const float*)d_in[0];
    const float* seg   = (const float*)d_in[1];
    const float* Wq    = (const float*)d_in[2];
    const float* bq    = (const float*)d_in[3];
    const float* Wk    = (const float*)d_in[4];
    const float* bk    = (const float*)d_in[5];
    const float* Wv    = (const float*)d_in[6];
    const float* bv    = (const float*)d_in[7];
    float* out = (float*)d_out;

    cudaFuncSetAttribute(flash_kernel, cudaFuncAttributeMaxDynamicSharedMemorySize,
                         FSM_BYTES);

    norm_kernel<<<BZ * LQ, 128>>>(query);
    pm_kernel<<<1280, 256>>>(query, seg, Wq, Wk, Wv, bq, bk, bv);
    flash_kernel<<<dim3(8, 64), 256, FSM_BYTES>>>(query, out);
}

// round 7
// speedup vs baseline: 4.2221x; 1.0511x over previous
#include <cuda_runtime.h>
#include <math.h>
#include <stdint.h>

#define LQ 1024
#define BZ 8
#define D  512
#define NH 8
#define DH 64
#define IOU_THR 0.2f
#define COS_THR 0.2f
#define NEGF -3.402823466e38f

#define SSTR 36   // pm smem stride (floats): 144B = 16 mod 128 -> LDSM conflict-free
#define FSTR 68   // flash Q/K stride: 272B = 16 mod 128 -> LDSM conflict-free
#define VSTR 72   // flash V stride: 288B = 32 mod 128 -> LDS.64 conflict-free

// ---------------- scratch (static device globals; no allocations) ----------
__device__ float g_Q[(size_t)BZ * LQ * D];                 // natural layout, tf32-rounded
__device__ float g_K[(size_t)BZ * LQ * D];
__device__ float g_Vt[(size_t)BZ * NH * DH * LQ];          // [bh][dh][Lq], tf32-rounded
__device__ float g_norm[BZ * LQ];
__device__ unsigned char g_mask[(size_t)BZ * LQ * LQ];     // 1 = masked

__device__ __forceinline__ float tf32r(float x) {
    float y;
    asm("cvt.rna.tf32.f32 %0, %1;" : "=f"(y) : "f"(x));
    return y;
}
__device__ __forceinline__ uint32_t smem_u32(const void* p) {
    uint32_t a;
    asm("{ .reg .u64 t; cvta.to.shared.u64 t, %1; cvt.u32.u64 %0, t; }"
        : "=r"(a) : "l"(p));
    return a;
}

#define MMA_TF32(c0, c1, c2, c3, a0, a1, a2, a3, b0, b1) \
    asm volatile("mma.sync.aligned.m16n8k8.row.col.f32.tf32.tf32.f32 " \
        "{%0,%1,%2,%3}, {%4,%5,%6,%7}, {%8,%9}, {%0,%1,%2,%3};" \
        : "+f"(c0), "+f"(c1), "+f"(c2), "+f"(c3) \
        : "r"(a0), "r"(a1), "r"(a2), "r"(a3), "r"(b0), "r"(b1))

// tf32-as-b16 ldmatrix: one x4 = 16 rows x 8 tf32 cols (A-frag) or
// 2 B-frag pairs, with the standard lane->register mapping.
#define LDSM_X4(d0, d1, d2, d3, addr) \
    asm volatile("ldmatrix.sync.aligned.m8n8.x4.shared.b16 {%0,%1,%2,%3}, [%4];" \
        : "=r"(d0), "=r"(d1), "=r"(d2), "=r"(d3) : "r"(addr))

__device__ __forceinline__ float warp_sum(float v) {
#pragma unroll
    for (int o = 16; o > 0; o >>= 1) v += __shfl_xor_sync(0xffffffffu, v, o);
    return v;
}

// ==================== tf32 GEMM core with LDSM fragments ====================
// C[128,128] = A[128,K] @ B[128,K]^T; 8 warps (2m x 4n), warp tile 64x32.
__device__ __forceinline__ void mma_chunk_ldsm(uint32_t As_u, uint32_t Bs_u,
                                               int wm, int wn, int lane,
                                               float (&acc)[4][4][4]) {
    // A: rows wm*64 + mf*16 + (lane&15), col-half (lane>>4)&1
    const uint32_t a_base = As_u +
        ((wm * 64 + (lane & 15)) * SSTR + ((lane >> 4) & 1) * 4) * 4;
    // B pair p: n-rows (wn*4 + p*2 + ((lane>>4)&1))*8 + (lane&7), k-half (lane>>3)&1
    const uint32_t b_base = Bs_u +
        (((wn * 4 + ((lane >> 4) & 1)) * 8 + (lane & 7)) * SSTR + ((lane >> 3) & 1) * 4) * 4;
#pragma unroll
    for (int ks = 0; ks < 4; ks++) {
        uint32_t a[4][4];
#pragma unroll
        for (int mf = 0; mf < 4; mf++)
            LDSM_X4(a[mf][0], a[mf][1], a[mf][2], a[mf][3],
                    a_base + (mf * 16 * SSTR) * 4 + ks * 32);
        uint32_t bfr[2][4];
#pragma unroll
        for (int p = 0; p < 2; p++)
            LDSM_X4(bfr[p][0], bfr[p][1], bfr[p][2], bfr[p][3],
                    b_base + (p * 16 * SSTR) * 4 + ks * 32);
#pragma unroll
        for (int mf = 0; mf < 4; mf++)
#pragma unroll
            for (int nf = 0; nf < 4; nf++) {
                uint32_t b0 = bfr[nf >> 1][(nf & 1) * 2];
                uint32_t b1 = bfr[nf >> 1][(nf & 1) * 2 + 1];
                MMA_TF32(acc[mf][nf][0], acc[mf][nf][1], acc[mf][nf][2], acc[mf][nf][3],
                         a[mf][0], a[mf][1], a[mf][2], a[mf][3], b0, b1);
            }
    }
}

template <int NCH>
__device__ __forceinline__ void gemm_mma(const float* __restrict__ Ab, int Astr,
                                         const float* __restrict__ Bb, int Bstr,
                                         float* As, float* Bs,
                                         float (&acc)[4][4][4]) {
    const int tid = threadIdx.x;
    const int w = tid >> 5, lane = tid & 31;
    const int wm = w & 1, wn = w >> 1;
    const uint32_t As_u = smem_u32(As), Bs_u = smem_u32(Bs);
    for (int it = 0; it < NCH; ++it) {
        if (it) __syncthreads();
#pragma unroll
        for (int i = 0; i < 4; i++) {
            int idx = tid + i * 256;
            int r = idx >> 3, c4 = idx & 7;
            float4 v = *(const float4*)(Ab + (size_t)r * Astr + it * 32 + c4 * 4);
            v.x = tf32r(v.x); v.y = tf32r(v.y); v.z = tf32r(v.z); v.w = tf32r(v.w);
            *(float4*)&As[r * SSTR + c4 * 4] = v;
        }
#pragma unroll
        for (int i = 0; i < 4; i++) {
            int idx = tid + i * 256;
            int r = idx >> 3, c4 = idx & 7;
            float4 v = *(const float4*)(Bb + (size_t)r * Bstr + it * 32 + c4 * 4);
            v.x = tf32r(v.x); v.y = tf32r(v.y); v.z = tf32r(v.z); v.w = tf32r(v.w);
            *(float4*)&Bs[r * SSTR + c4 * 4] = v;
        }
        __syncthreads();
        mma_chunk_ldsm(As_u, Bs_u, wm, wn, lane, acc);
    }
}

// ---------------- row norms of h (fp32 exact) -------------------------------
__global__ void norm_kernel(const float* __restrict__ q) {
    int row = blockIdx.x;
    int b = row / LQ, l = row % LQ;
    const float* h = q + ((size_t)l * BZ + b) * D;
    float s = 0.f;
    for (int k = threadIdx.x; k < D; k += 128) {
        float v = h[k];
        s = fmaf(v, v, s);
    }
    __shared__ float red[4];
    s = warp_sum(s);
    int wid = threadIdx.x >> 5, lane = threadIdx.x & 31;
    if (lane == 0) red[wid] = s;
    __syncthreads();
    if (threadIdx.x == 0)
        g_norm[row] = fmaxf(sqrtf(red[0] + red[1] + red[2] + red[3]), 1e-8f);
}

// ================ fused proj (bid<768) + mask (bid>=768) ====================
__global__ __launch_bounds__(256, 2) void pm_kernel(
    const float* __restrict__ q, const float* __restrict__ seg,
    const float* __restrict__ Wq, const float* __restrict__ Wk, const float* __restrict__ Wv,
    const float* __restrict__ bq, const float* __restrict__ bk, const float* __restrict__ bv) {
    __shared__ float As[128 * SSTR];
    __shared__ float Bs[128 * SSTR];
    const int tid = threadIdx.x;
    const int w = tid >> 5, lane = tid & 31;
    const int wm = w & 1, wn = w >> 1;
    const int bid = blockIdx.x;

    if (bid < 768) {   // ---------------- projection path ----------------
        const int which = bid >> 8;
        const int rem = bid & 255;
        const int col0 = (rem & 3) * 128;
        const int y = rem >> 2;
        const int b = y >> 3;
        const int i0 = (y & 7) * 128;
        const float* W = (which == 0) ? Wq : (which == 1) ? Wk : Wv;
        const float* bias = (which == 0) ? bq : (which == 1) ? bk : bv;

        float acc[4][4][4] = {};
        const float* Ab = q + (size_t)i0 * (BZ * D) + (size_t)b * D;
        const float* Bb = W + (size_t)col0 * D;
        gemm_mma<D / 32>(Ab, BZ * D, Bb, D, As, Bs, acc);

        const int rbase = wm * 64 + (lane >> 2);
        const int cbase = wn * 32 + (lane & 3) * 2;
        if (which < 2) {
            float* out = (which == 0) ? g_Q : g_K;
#pragma unroll
            for (int mf = 0; mf < 4; mf++) {
                int r0 = i0 + rbase + mf * 16;
#pragma unroll
                for (int nf = 0; nf < 4; nf++) {
                    int c = col0 + cbase + nf * 8;
                    float2 bb = *(const float2*)&bias[c];
                    *(float2*)&out[((size_t)(b * LQ + r0)) * D + c] =
                        make_float2(tf32r(acc[mf][nf][0] + bb.x),
                                    tf32r(acc[mf][nf][1] + bb.y));
                    *(float2*)&out[((size_t)(b * LQ + r0 + 8)) * D + c] =
                        make_float2(tf32r(acc[mf][nf][2] + bb.x),
                                    tf32r(acc[mf][nf][3] + bb.y));
                }
            }
        } else {   // V -> transposed, tf32-rounded
#pragma unroll
            for (int mf = 0; mf < 4; mf++) {
                int r0 = i0 + rbase + mf * 16;
#pragma unroll
                for (int nf = 0; nf < 4; nf++) {
                    int n = col0 + cbase + nf * 8;
                    float2 bb = *(const float2*)&bias[n];
                    size_t o0 = ((size_t)(b * NH + (n >> 6)) * DH + (n & 63)) * LQ;
                    size_t o1 = ((size_t)(b * NH + ((n + 1) >> 6)) * DH + ((n + 1) & 63)) * LQ;
                    g_Vt[o0 + r0]     = tf32r(acc[mf][nf][0] + bb.x);
                    g_Vt[o1 + r0]     = tf32r(acc[mf][nf][1] + bb.y);
                    g_Vt[o0 + r0 + 8] = tf32r(acc[mf][nf][2] + bb.x);
                    g_Vt[o1 + r0 + 8] = tf32r(acc[mf][nf][3] + bb.y);
                }
            }
        }
    } else {   // ---------------- mask path ----------------
        const int mb = bid - 768;
        const int j0 = (mb & 7) * 128;
        const int i0 = ((mb >> 3) & 7) * 128;
        const int b = mb >> 6;

        float acc[4][4][4] = {};
        const float* Ab = q + (size_t)i0 * (BZ * D) + (size_t)b * D;
        const float* Bb = q + (size_t)j0 * (BZ * D) + (size_t)b * D;
        gemm_mma<D / 32>(Ab, BZ * D, Bb, BZ * D, As, Bs, acc);

        __syncthreads();
        float4* auxr = (float4*)As;
        float4* auxc = (float4*)(As + 512);
        if (tid < 128) {
            int r = i0 + tid;
            float2 sg = *(const float2*)(seg + ((size_t)b * LQ + r) * 2);
            auxr[tid] = make_float4(g_norm[b * LQ + r], sg.x - 0.5f * sg.y,
                                    sg.x + 0.5f * sg.y, sg.y);
        } else {
            int t = tid - 128;
            int c = j0 + t;
            float2 sg = *(const float2*)(seg + ((size_t)b * LQ + c) * 2);
            auxc[t] = make_float4(g_norm[b * LQ + c], sg.x - 0.5f * sg.y,
                                  sg.x + 0.5f * sg.y, sg.y);
        }
        __syncthreads();

        const int rbase = wm * 64 + (lane >> 2);
        const int cbase = wn * 32 + (lane & 3) * 2;
#pragma unroll
        for (int mf = 0; mf < 4; mf++) {
#pragma unroll
            for (int half = 0; half < 2; half++) {
                int rl_ = rbase + mf * 16 + half * 8;
                float4 ar = auxr[rl_];
                int rg = i0 + rl_;
#pragma unroll
                for (int nf = 0; nf < 4; nf++) {
                    int cl_ = cbase + nf * 8;
                    uchar2 mm;
#pragma unroll
                    for (int e = 0; e < 2; e++) {
                        float4 ac = auxc[cl_ + e];
                        float cosv = acc[mf][nf][half * 2 + e] / (ar.x * ac.x);
                        float inter = fmaxf(fminf(ar.z, ac.z) - fmaxf(ar.y, ac.y), 0.f);
                        float iou = inter / (ar.w + ac.w - inter);
                        int cg = j0 + cl_ + e;
                        bool adj = (cosv > COS_THR) && ((iou <= IOU_THR) || (rg == cg));
                        if (e == 0) mm.x = adj ? 0 : 1; else mm.y = adj ? 0 : 1;
                    }
                    *(uchar2*)&g_mask[((size_t)(b * LQ + rg)) * LQ + j0 + cl_] = mm;
                }
            }
        }
    }
}

// ==================== fused attention (flash, LDSM QK, reg P) ===============
// smem: sQ[128][FSTR] | sK[64][FSTR] | sV[64][VSTR]
#define FSM_BYTES ((128 * FSTR + 64 * FSTR + 64 * VSTR) * 4)

__global__ __launch_bounds__(256, 2) void flash_kernel(const float* __restrict__ q,
                                                       float* __restrict__ out) {
    extern __shared__ float sm[];
    float* sQ = sm;
    float* sK = sQ + 128 * FSTR;
    float* sV = sK + 64 * FSTR;

    const int tid = threadIdx.x;
    const int w = tid >> 5, lane = tid & 31;
    const int rr = lane >> 2, cc = lane & 3;
    const int bh = blockIdx.y, b = bh >> 3, h = bh & 7;
    const int i0 = blockIdx.x * 128;
    const int wbase = w * 16;

    // stage Q (pre-rounded, natural)
#pragma unroll
    for (int i = 0; i < 8; i++) {
        int idx = tid + i * 256;
        int r = idx >> 4, c4 = idx & 15;
        *(float4*)&sQ[r * FSTR + c4 * 4] =
            *(const float4*)&g_Q[((size_t)(b * LQ + i0 + r)) * D + h * DH + c4 * 4];
    }

    // LDSM base addresses
    const uint32_t sQu = smem_u32(sQ), sKu = smem_u32(sK);
    const uint32_t q_base = sQu +
        ((wbase + (lane & 15)) * FSTR + ((lane >> 4) & 1) * 4) * 4;
    const uint32_t k_base = sKu +
        ((((lane >> 4) & 1) * 8 + (lane & 7)) * FSTR + ((lane >> 3) & 1) * 4) * 4;

    float Oacc[8][4] = {};
    float m0 = NEGF, m1 = NEGF, l0 = 0.f, l1 = 0.f;
    const int r0g = i0 + wbase + rr, r1g = r0g + 8;
    const unsigned char* mrow0 = g_mask + ((size_t)(b * LQ + r0g)) * LQ;
    const unsigned char* mrow1 = g_mask + ((size_t)(b * LQ + r1g)) * LQ;

    for (int j0 = 0; j0 < LQ; j0 += 64) {
        __syncthreads();
#pragma unroll
        for (int i = 0; i < 4; i++) {           // stage K, V (pre-rounded)
            int idx = tid + i * 256;
            int r = idx >> 4, c4 = idx & 15;
            *(float4*)&sK[r * FSTR + c4 * 4] =
                *(const float4*)&g_K[((size_t)(b * LQ + j0 + r)) * D + h * DH + c4 * 4];
            *(float4*)&sV[r * VSTR + c4 * 4] =
                *(const float4*)&g_Vt[((size_t)bh * DH + r) * LQ + j0 + c4 * 4];
        }
        __syncthreads();

        // S = Q K^T via LDSM fragments
        float Sacc[8][4] = {};
#pragma unroll
        for (int ks = 0; ks < 8; ks++) {
            uint32_t a0, a1, a2, a3;
            LDSM_X4(a0, a1, a2, a3, q_base + ks * 32);
#pragma unroll
            for (int p = 0; p < 4; p++) {
                uint32_t f0, f1, f2, f3;
                LDSM_X4(f0, f1, f2, f3, k_base + (p * 16 * FSTR) * 4 + ks * 32);
                MMA_TF32(Sacc[p * 2][0], Sacc[p * 2][1], Sacc[p * 2][2], Sacc[p * 2][3],
                         a0, a1, a2, a3, f0, f1);
                MMA_TF32(Sacc[p * 2 + 1][0], Sacc[p * 2 + 1][1],
                         Sacc[p * 2 + 1][2], Sacc[p * 2 + 1][3],
                         a0, a1, a2, a3, f2, f3);
            }
        }

        // scale + mask + tile row max
        float mx0 = NEGF, mx1 = NEGF;
#pragma unroll
        for (int nf = 0; nf < 8; nf++) {
            int c = j0 + nf * 8 + cc * 2;
            uchar2 ma = *(const uchar2*)&mrow0[c];
            uchar2 mb = *(const uchar2*)&mrow1[c];
            Sacc[nf][0] = ma.x ? NEGF : Sacc[nf][0] * 0.125f;
            Sacc[nf][1] = ma.y ? NEGF : Sacc[nf][1] * 0.125f;
            Sacc[nf][2] = mb.x ? NEGF : Sacc[nf][2] * 0.125f;
            Sacc[nf][3] = mb.y ? NEGF : Sacc[nf][3] * 0.125f;
            mx0 = fmaxf(mx0, fmaxf(Sacc[nf][0], Sacc[nf][1]));
            mx1 = fmaxf(mx1, fmaxf(Sacc[nf][2], Sacc[nf][3]));
        }
        mx0 = fmaxf(mx0, __shfl_xor_sync(0xffffffffu, mx0, 1));
        mx0 = fmaxf(mx0, __shfl_xor_sync(0xffffffffu, mx0, 2));
        mx1 = fmaxf(mx1, __shfl_xor_sync(0xffffffffu, mx1, 1));
        mx1 = fmaxf(mx1, __shfl_xor_sync(0xffffffffu, mx1, 2));

        float nm0 = fmaxf(m0, mx0), nm1 = fmaxf(m1, mx1);
        float al0 = __expf(m0 - nm0), al1 = __expf(m1 - nm1);
        m0 = nm0; m1 = nm1;

        float rs0 = 0.f, rs1 = 0.f;
#pragma unroll
        for (int nf = 0; nf < 8; nf++) {
            float p00 = __expf(Sacc[nf][0] - nm0);
            float p01 = __expf(Sacc[nf][1] - nm0);
            float p10 = __expf(Sacc[nf][2] - nm1);
            float p11 = __expf(Sacc[nf][3] - nm1);
            rs0 += p00 + p01; rs1 += p10 + p11;
            Sacc[nf][0] = tf32r(p00); Sacc[nf][1] = tf32r(p01);
            Sacc[nf][2] = tf32r(p10); Sacc[nf][3] = tf32r(p11);
            Oacc[nf][0] *= al0; Oacc[nf][1] *= al0;
            Oacc[nf][2] *= al1; Oacc[nf][3] *= al1;
        }
        rs0 += __shfl_xor_sync(0xffffffffu, rs0, 1);
        rs0 += __shfl_xor_sync(0xffffffffu, rs0, 2);
        rs1 += __shfl_xor_sync(0xffffffffu, rs1, 1);
        rs1 += __shfl_xor_sync(0xffffffffu, rs1, 2);
        l0 = l0 * al0 + rs0;
        l1 = l1 * al1 + rs1;

        // O += P @ V : A-frag = renamed C-frag {c0,c2,c1,c3}; k-slot cc <-> P col 2cc,
        // slot cc+4 <-> col 2cc+1 -> V rows (2cc, 2cc+1) = natural LDS.64
#pragma unroll
        for (int ks = 0; ks < 8; ks++) {
            uint32_t a0 = __float_as_uint(Sacc[ks][0]);
            uint32_t a1 = __float_as_uint(Sacc[ks][2]);
            uint32_t a2 = __float_as_uint(Sacc[ks][1]);
            uint32_t a3 = __float_as_uint(Sacc[ks][3]);
#pragma unroll
            for (int nf = 0; nf < 8; nf++) {
                float2 bb = *(const float2*)(sV + (nf * 8 + rr) * VSTR + ks * 8 + 2 * cc);
                MMA_TF32(Oacc[nf][0], Oacc[nf][1], Oacc[nf][2], Oacc[nf][3],
                         a0, a1, a2, a3, __float_as_uint(bb.x), __float_as_uint(bb.y));
            }
        }
    }

    // epilogue
    float inv0 = 1.0f / l0, inv1 = 1.0f / l1;
#pragma unroll
    for (int nf = 0; nf < 8; nf++) {
        int c = h * DH + nf * 8 + cc * 2;
        size_t o0 = ((size_t)r0g * BZ + b) * D + c;
        size_t o1 = ((size_t)r1g * BZ + b) * D + c;
        float2 q0 = *(const float2*)&q[o0];
        float2 q1 = *(const float2*)&q[o1];
        *(float2*)&out[o0] = make_float2(q0.x + Oacc[nf][0] * inv0,
                                         q0.y + Oacc[nf][1] * inv0);
        *(float2*)&out[o1] = make_float2(q1.x + Oacc[nf][2] * inv1,
                                         q1.y + Oacc[nf][3] * inv1);
    }
}

// ---------------- launch ----------------------------------------------------
extern "C" void kernel_launch(void* const* d_in, const int* in_sizes, int n_in,
                              void* d_out, int out_size) {
    const float* query = (const float*)d_in[0];
    const float* seg   = (const float*)d_in[1];
    const float* Wq    = (const float*)d_in[2];
    const float* bq    = (const float*)d_in[3];
    const float* Wk    = (const float*)d_in[4];
    const float* bk    = (const float*)d_in[5];
    const float* Wv    = (const float*)d_in[6];
    const float* bv    = (const float*)d_in[7];
    float* out = (float*)d_out;

    cudaFuncSetAttribute(flash_kernel, cudaFuncAttributeMaxDynamicSharedMemorySize,
                         FSM_BYTES);

    norm_kernel<<<BZ * LQ, 128>>>(query);
    pm_kernel<<<1280, 256>>>(query, seg, Wq, Wk, Wv, bq, bk, bv);
    flash_kernel<<<dim3(8, 64), 256, FSM_BYTES>>>(query, out);
}

// round 8
// speedup vs baseline: 7.1393x; 1.6909x over previous
#include <cuda_runtime.h>
#include <math.h>
#include <stdint.h>

#define LQ 1024
#define BZ 8
#define D  512
#define NH 8
#define DH 64
#define IOU_THR 0.2f
#define COS_THR 0.2f
#define NEGF -3.402823466e38f

#define SSTR 36   // pm smem stride (floats): 144B = 16 mod 128 -> LDSM conflict-free
#define FSTR 68   // flash Q/K stride: 272B = 16 mod 128 -> LDSM conflict-free
#define VSTR 72   // flash V stride: 288B = 32 mod 128 -> LDS.64 conflict-free

// ---------------- scratch (static device globals; no allocations) ----------
__device__ float g_hr[(size_t)BZ * LQ * D];                // tf32-rounded h (q layout)
__device__ float g_Wr[3 * 512 * 512];                      // tf32-rounded Wq|Wk|Wv
__device__ float g_Q[(size_t)BZ * LQ * D];                 // tf32-rounded
__device__ float g_K[(size_t)BZ * LQ * D];
__device__ float g_Vt[(size_t)BZ * NH * DH * LQ];          // [bh][dh][Lq], tf32-rounded
__device__ float g_norm[BZ * LQ];
__device__ unsigned char g_mask[(size_t)BZ * LQ * LQ];     // 1 = masked
__device__ unsigned char g_live[BZ * 8 * 16];              // [b][i128][j64] any-adj flag

__device__ __forceinline__ float tf32r(float x) {
    float y;
    asm("cvt.rna.tf32.f32 %0, %1;" : "=f"(y) : "f"(x));
    return y;
}
__device__ __forceinline__ uint32_t smem_u32(const void* p) {
    uint32_t a;
    asm("{ .reg .u64 t; cvta.to.shared.u64 t, %1; cvt.u32.u64 %0, t; }"
        : "=r"(a) : "l"(p));
    return a;
}

#define MMA_TF32(c0, c1, c2, c3, a0, a1, a2, a3, b0, b1) \
    asm volatile("mma.sync.aligned.m16n8k8.row.col.f32.tf32.tf32.f32 " \
        "{%0,%1,%2,%3}, {%4,%5,%6,%7}, {%8,%9}, {%0,%1,%2,%3};" \
        : "+f"(c0), "+f"(c1), "+f"(c2), "+f"(c3) \
        : "r"(a0), "r"(a1), "r"(a2), "r"(a3), "r"(b0), "r"(b1))

#define LDSM_X4(d0, d1, d2, d3, addr) \
    asm volatile("ldmatrix.sync.aligned.m8n8.x4.shared.b16 {%0,%1,%2,%3}, [%4];" \
        : "=r"(d0), "=r"(d1), "=r"(d2), "=r"(d3) : "r"(addr))

#define CPASYNC16(dst, src) \
    asm volatile("cp.async.ca.shared.global [%0], [%1], 16;" \
                 :: "r"(dst), "l"(src) : "memory")
#define CPCOMMIT() asm volatile("cp.async.commit_group;" ::: "memory")
#define CPWAIT(n)  asm volatile("cp.async.wait_group %0;" :: "n"(n) : "memory")

__device__ __forceinline__ float warp_sum(float v) {
#pragma unroll
    for (int o = 16; o > 0; o >>= 1) v += __shfl_xor_sync(0xffffffffu, v, o);
    return v;
}

// ==================== tf32 GEMM core: LDSM frags + cp.async =================
__device__ __forceinline__ void mma_chunk_ldsm(uint32_t As_u, uint32_t Bs_u,
                                               int wm, int wn, int lane,
                                               float (&acc)[4][4][4]) {
    const uint32_t a_base = As_u +
        ((wm * 64 + (lane & 15)) * SSTR + ((lane >> 4) & 1) * 4) * 4;
    const uint32_t b_base = Bs_u +
        (((wn * 4 + ((lane >> 4) & 1)) * 8 + (lane & 7)) * SSTR + ((lane >> 3) & 1) * 4) * 4;
#pragma unroll
    for (int ks = 0; ks < 4; ks++) {
        uint32_t a[4][4];
#pragma unroll
        for (int mf = 0; mf < 4; mf++)
            LDSM_X4(a[mf][0], a[mf][1], a[mf][2], a[mf][3],
                    a_base + (mf * 16 * SSTR) * 4 + ks * 32);
        uint32_t bfr[2][4];
#pragma unroll
        for (int p = 0; p < 2; p++)
            LDSM_X4(bfr[p][0], bfr[p][1], bfr[p][2], bfr[p][3],
                    b_base + (p * 16 * SSTR) * 4 + ks * 32);
#pragma unroll
        for (int mf = 0; mf < 4; mf++)
#pragma unroll
            for (int nf = 0; nf < 4; nf++) {
                uint32_t b0 = bfr[nf >> 1][(nf & 1) * 2];
                uint32_t b1 = bfr[nf >> 1][(nf & 1) * 2 + 1];
                MMA_TF32(acc[mf][nf][0], acc[mf][nf][1], acc[mf][nf][2], acc[mf][nf][3],
                         a[mf][0], a[mf][1], a[mf][2], a[mf][3], b0, b1);
            }
    }
}

#define CHUNK_BYTES (128 * SSTR * 4)

__device__ __forceinline__ void issue_chunk(uint32_t base,
                                            const float* __restrict__ Ab, int Astr,
                                            const float* __restrict__ Bb, int Bstr,
                                            int it, int tid) {
    const int p = it & 1;
    const uint32_t aoff = base + (uint32_t)(p * CHUNK_BYTES);
    const uint32_t boff = base + (uint32_t)((2 + p) * CHUNK_BYTES);
#pragma unroll
    for (int i = 0; i < 4; i++) {
        int idx = tid + i * 256;
        int r = idx >> 3, c4 = idx & 7;
        CPASYNC16(aoff + (r * SSTR + c4 * 4) * 4, Ab + (size_t)r * Astr + it * 32 + c4 * 4);
        CPASYNC16(boff + (r * SSTR + c4 * 4) * 4, Bb + (size_t)r * Bstr + it * 32 + c4 * 4);
    }
}

template <int NCH>
__device__ __forceinline__ void gemm_async(const float* __restrict__ Ab, int Astr,
                                           const float* __restrict__ Bb, int Bstr,
                                           float* smem, float (&acc)[4][4][4]) {
    const int tid = threadIdx.x;
    const int w = tid >> 5, lane = tid & 31;
    const int wm = w & 1, wn = w >> 1;
    const uint32_t base = smem_u32(smem);
    issue_chunk(base, Ab, Astr, Bb, Bstr, 0, tid);
    CPCOMMIT();
    for (int it = 0; it < NCH; ++it) {
        const int p = it & 1;
        if (it + 1 < NCH) {
            issue_chunk(base, Ab, Astr, Bb, Bstr, it + 1, tid);
            CPCOMMIT();
            CPWAIT(1);
        } else {
            CPWAIT(0);
        }
        __syncthreads();
        mma_chunk_ldsm(base + p * CHUNK_BYTES, base + (2 + p) * CHUNK_BYTES,
                       wm, wn, lane, acc);
        __syncthreads();
    }
}

// ---------------- prep: norms + tf32-rounded h and W ------------------------
__global__ void prep_kernel(const float* __restrict__ q,
                            const float* __restrict__ Wq,
                            const float* __restrict__ Wk,
                            const float* __restrict__ Wv) {
    const int bid = blockIdx.x, tid = threadIdx.x;
    if (bid < 4096) {
        const int half = tid >> 7;          // row within block
        const int t = tid & 127;
        const int row = bid * 2 + half;     // b*LQ + l
        const int b = row >> 10, l = row & 1023;
        const size_t o = ((size_t)l * BZ + b) * D + t * 4;
        float4 v = *(const float4*)(q + o);
        *(float4*)(g_hr + o) = make_float4(tf32r(v.x), tf32r(v.y), tf32r(v.z), tf32r(v.w));
        float s = v.x * v.x + v.y * v.y + v.z * v.z + v.w * v.w;
        s = warp_sum(s);
        __shared__ float red[8];
        if ((t & 31) == 0) red[half * 4 + (t >> 5)] = s;
        __syncthreads();
        if (t == 0) {
            float tot = red[half * 4] + red[half * 4 + 1] +
                        red[half * 4 + 2] + red[half * 4 + 3];
            g_norm[row] = fmaxf(sqrtf(tot), 1e-8f);
        }
    } else {
        const int idx = (bid - 4096) * 256 + tid;      // float4 index
        const int which = idx >> 16;
        const int off = (idx & 65535) * 4;
        const float* W = (which == 0) ? Wq : (which == 1) ? Wk : Wv;
        float4 v = *(const float4*)(W + off);
        *(float4*)(g_Wr + which * 262144 + off) =
            make_float4(tf32r(v.x), tf32r(v.y), tf32r(v.z), tf32r(v.w));
    }
}

// ================ fused proj (bid<768) + mask (bid>=768) ====================
// dynamic smem: 4 chunk buffers (A0 A1 B0 B1), 73728 bytes
__global__ __launch_bounds__(256, 2) void pm_kernel(
    const float* __restrict__ seg,
    const float* __restrict__ bq, const float* __restrict__ bk, const float* __restrict__ bv) {
    extern __shared__ float smp[];
    const int tid = threadIdx.x;
    const int w = tid >> 5, lane = tid & 31;
    const int wm = w & 1, wn = w >> 1;
    const int bid = blockIdx.x;

    if (bid < 768) {   // ---------------- projection path ----------------
        const int which = bid >> 8;
        const int rem = bid & 255;
        const int col0 = (rem & 3) * 128;
        const int y = rem >> 2;
        const int b = y >> 3;
        const int i0 = (y & 7) * 128;
        const float* bias = (which == 0) ? bq : (which == 1) ? bk : bv;

        float acc[4][4][4] = {};
        const float* Ab = g_hr + (size_t)i0 * (BZ * D) + (size_t)b * D;
        const float* Bb = g_Wr + which * 262144 + (size_t)col0 * D;
        gemm_async<D / 32>(Ab, BZ * D, Bb, D, smp, acc);

        const int rbase = wm * 64 + (lane >> 2);
        const int cbase = wn * 32 + (lane & 3) * 2;
        if (which < 2) {
            float* out = (which == 0) ? g_Q : g_K;
#pragma unroll
            for (int mf = 0; mf < 4; mf++) {
                int r0 = i0 + rbase + mf * 16;
#pragma unroll
                for (int nf = 0; nf < 4; nf++) {
                    int c = col0 + cbase + nf * 8;
                    float2 bb = *(const float2*)&bias[c];
                    *(float2*)&out[((size_t)(b * LQ + r0)) * D + c] =
                        make_float2(tf32r(acc[mf][nf][0] + bb.x),
                                    tf32r(acc[mf][nf][1] + bb.y));
                    *(float2*)&out[((size_t)(b * LQ + r0 + 8)) * D + c] =
                        make_float2(tf32r(acc[mf][nf][2] + bb.x),
                                    tf32r(acc[mf][nf][3] + bb.y));
                }
            }
        } else {   // V -> transposed, tf32-rounded
#pragma unroll
            for (int mf = 0; mf < 4; mf++) {
                int r0 = i0 + rbase + mf * 16;
#pragma unroll
                for (int nf = 0; nf < 4; nf++) {
                    int n = col0 + cbase + nf * 8;
                    float2 bb = *(const float2*)&bias[n];
                    size_t o0 = ((size_t)(b * NH + (n >> 6)) * DH + (n & 63)) * LQ;
                    size_t o1 = ((size_t)(b * NH + ((n + 1) >> 6)) * DH + ((n + 1) & 63)) * LQ;
                    g_Vt[o0 + r0]     = tf32r(acc[mf][nf][0] + bb.x);
                    g_Vt[o1 + r0]     = tf32r(acc[mf][nf][1] + bb.y);
                    g_Vt[o0 + r0 + 8] = tf32r(acc[mf][nf][2] + bb.x);
                    g_Vt[o1 + r0 + 8] = tf32r(acc[mf][nf][3] + bb.y);
                }
            }
        }
    } else {   // ---------------- mask path ----------------
        const int mb = bid - 768;
        const int j0 = (mb & 7) * 128;
        const int i0 = ((mb >> 3) & 7) * 128;
        const int b = mb >> 6;

        float acc[4][4][4] = {};
        const float* Ab = g_hr + (size_t)i0 * (BZ * D) + (size_t)b * D;
        const float* Bb = g_hr + (size_t)j0 * (BZ * D) + (size_t)b * D;
        gemm_async<D / 32>(Ab, BZ * D, Bb, BZ * D, smp, acc);

        __shared__ unsigned int liveflag[2];
        if (tid < 2) liveflag[tid] = 0;
        __syncthreads();

        float4* auxr = (float4*)smp;
        float4* auxc = (float4*)(smp + 512);
        const float* sgb = seg + (size_t)b * LQ * 2;
        if (tid < 128) {
            int r = i0 + tid;
            float2 sg = *(const float2*)(sgb + r * 2);
            auxr[tid] = make_float4(g_norm[b * LQ + r], sg.x - 0.5f * sg.y,
                                    sg.x + 0.5f * sg.y, sg.y);
        } else {
            int t = tid - 128;
            int c = j0 + t;
            float2 sg = *(const float2*)(sgb + c * 2);
            auxc[t] = make_float4(g_norm[b * LQ + c], sg.x - 0.5f * sg.y,
                                  sg.x + 0.5f * sg.y, sg.y);
        }
        __syncthreads();

        const int rbase = wm * 64 + (lane >> 2);
        const int cbase = wn * 32 + (lane & 3) * 2;
        unsigned int any = 0;
#pragma unroll
        for (int mf = 0; mf < 4; mf++) {
#pragma unroll
            for (int half = 0; half < 2; half++) {
                int rl_ = rbase + mf * 16 + half * 8;
                float4 ar = auxr[rl_];
                int rg = i0 + rl_;
#pragma unroll
                for (int nf = 0; nf < 4; nf++) {
                    int cl_ = cbase + nf * 8;
                    uchar2 mm;
#pragma unroll
                    for (int e = 0; e < 2; e++) {
                        float4 ac = auxc[cl_ + e];
                        float cosv = acc[mf][nf][half * 2 + e] / (ar.x * ac.x);
                        float inter = fmaxf(fminf(ar.z, ac.z) - fmaxf(ar.y, ac.y), 0.f);
                        float iou = inter / (ar.w + ac.w - inter);
                        int cg = j0 + cl_ + e;
                        bool adj = (cosv > COS_THR) && ((iou <= IOU_THR) || (rg == cg));
                        any |= (unsigned)adj;
                        if (e == 0) mm.x = adj ? 0 : 1; else mm.y = adj ? 0 : 1;
                    }
                    *(uchar2*)&g_mask[((size_t)(b * LQ + rg)) * LQ + j0 + cl_] = mm;
                }
            }
        }
        if (any) atomicOr(&liveflag[wn >> 1], 1u);
        __syncthreads();
        if (tid < 2)
            g_live[(b * 8 + (i0 >> 7)) * 16 + (j0 >> 6) + tid] =
                (unsigned char)liveflag[tid];
    }
}

// ==================== fused attention (flash, live-tile skip) ===============
#define FSM_BYTES ((128 * FSTR + 64 * FSTR + 64 * VSTR) * 4)

__global__ __launch_bounds__(256, 2) void flash_kernel(const float* __restrict__ q,
                                                       float* __restrict__ out) {
    extern __shared__ float sm[];
    float* sQ = sm;
    float* sK = sQ + 128 * FSTR;
    float* sV = sK + 64 * FSTR;

    const int tid = threadIdx.x;
    const int w = tid >> 5, lane = tid & 31;
    const int rr = lane >> 2, cc = lane & 3;
    const int bh = blockIdx.y, b = bh >> 3, h = bh & 7;
    const int i0 = blockIdx.x * 128;
    const int wbase = w * 16;

    // live-tile flags for this (b, i-tile): 16 bytes
    const uint4 fl4 = *(const uint4*)&g_live[(b * 8 + (i0 >> 7)) * 16];
    const unsigned int flags[4] = {fl4.x, fl4.y, fl4.z, fl4.w};

    // stage Q (pre-rounded, natural)
#pragma unroll
    for (int i = 0; i < 8; i++) {
        int idx = tid + i * 256;
        int r = idx >> 4, c4 = idx & 15;
        *(float4*)&sQ[r * FSTR + c4 * 4] =
            *(const float4*)&g_Q[((size_t)(b * LQ + i0 + r)) * D + h * DH + c4 * 4];
    }

    const uint32_t sQu = smem_u32(sQ), sKu = smem_u32(sK);
    const uint32_t q_base = sQu +
        ((wbase + (lane & 15)) * FSTR + ((lane >> 4) & 1) * 4) * 4;
    const uint32_t k_base = sKu +
        ((((lane >> 4) & 1) * 8 + (lane & 7)) * FSTR + ((lane >> 3) & 1) * 4) * 4;

    float Oacc[8][4] = {};
    float m0 = NEGF, m1 = NEGF, l0 = 0.f, l1 = 0.f;
    const int r0g = i0 + wbase + rr, r1g = r0g + 8;
    const unsigned char* mrow0 = g_mask + ((size_t)(b * LQ + r0g)) * LQ;
    const unsigned char* mrow1 = g_mask + ((size_t)(b * LQ + r1g)) * LQ;

    for (int jt = 0; jt < 16; jt++) {
        if (!((flags[jt >> 2] >> ((jt & 3) * 8)) & 0xffu)) continue;  // dead tile: exact skip
        const int j0 = jt * 64;
        __syncthreads();
#pragma unroll
        for (int i = 0; i < 4; i++) {           // stage K, V (pre-rounded)
            int idx = tid + i * 256;
            int r = idx >> 4, c4 = idx & 15;
            *(float4*)&sK[r * FSTR + c4 * 4] =
                *(const float4*)&g_K[((size_t)(b * LQ + j0 + r)) * D + h * DH + c4 * 4];
            *(float4*)&sV[r * VSTR + c4 * 4] =
                *(const float4*)&g_Vt[((size_t)bh * DH + r) * LQ + j0 + c4 * 4];
        }
        __syncthreads();

        // S = Q K^T via LDSM fragments
        float Sacc[8][4] = {};
#pragma unroll
        for (int ks = 0; ks < 8; ks++) {
            uint32_t a0, a1, a2, a3;
            LDSM_X4(a0, a1, a2, a3, q_base + ks * 32);
#pragma unroll
            for (int p = 0; p < 4; p++) {
                uint32_t f0, f1, f2, f3;
                LDSM_X4(f0, f1, f2, f3, k_base + (p * 16 * FSTR) * 4 + ks * 32);
                MMA_TF32(Sacc[p * 2][0], Sacc[p * 2][1], Sacc[p * 2][2], Sacc[p * 2][3],
                         a0, a1, a2, a3, f0, f1);
                MMA_TF32(Sacc[p * 2 + 1][0], Sacc[p * 2 + 1][1],
                         Sacc[p * 2 + 1][2], Sacc[p * 2 + 1][3],
                         a0, a1, a2, a3, f2, f3);
            }
        }

        // scale + mask + tile row max
        float mx0 = NEGF, mx1 = NEGF;
#pragma unroll
        for (int nf = 0; nf < 8; nf++) {
            int c = j0 + nf * 8 + cc * 2;
            uchar2 ma = *(const uchar2*)&mrow0[c];
            uchar2 mb = *(const uchar2*)&mrow1[c];
            Sacc[nf][0] = ma.x ? NEGF : Sacc[nf][0] * 0.125f;
            Sacc[nf][1] = ma.y ? NEGF : Sacc[nf][1] * 0.125f;
            Sacc[nf][2] = mb.x ? NEGF : Sacc[nf][2] * 0.125f;
            Sacc[nf][3] = mb.y ? NEGF : Sacc[nf][3] * 0.125f;
            mx0 = fmaxf(mx0, fmaxf(Sacc[nf][0], Sacc[nf][1]));
            mx1 = fmaxf(mx1, fmaxf(Sacc[nf][2], Sacc[nf][3]));
        }
        mx0 = fmaxf(mx0, __shfl_xor_sync(0xffffffffu, mx0, 1));
        mx0 = fmaxf(mx0, __shfl_xor_sync(0xffffffffu, mx0, 2));
        mx1 = fmaxf(mx1, __shfl_xor_sync(0xffffffffu, mx1, 1));
        mx1 = fmaxf(mx1, __shfl_xor_sync(0xffffffffu, mx1, 2));

        float nm0 = fmaxf(m0, mx0), nm1 = fmaxf(m1, mx1);
        float al0 = __expf(m0 - nm0), al1 = __expf(m1 - nm1);
        m0 = nm0; m1 = nm1;

        float rs0 = 0.f, rs1 = 0.f;
#pragma unroll
        for (int nf = 0; nf < 8; nf++) {
            float p00 = __expf(Sacc[nf][0] - nm0);
            float p01 = __expf(Sacc[nf][1] - nm0);
            float p10 = __expf(Sacc[nf][2] - nm1);
            float p11 = __expf(Sacc[nf][3] - nm1);
            rs0 += p00 + p01; rs1 += p10 + p11;
            Sacc[nf][0] = tf32r(p00); Sacc[nf][1] = tf32r(p01);
            Sacc[nf][2] = tf32r(p10); Sacc[nf][3] = tf32r(p11);
            Oacc[nf][0] *= al0; Oacc[nf][1] *= al0;
            Oacc[nf][2] *= al1; Oacc[nf][3] *= al1;
        }
        rs0 += __shfl_xor_sync(0xffffffffu, rs0, 1);
        rs0 += __shfl_xor_sync(0xffffffffu, rs0, 2);
        rs1 += __shfl_xor_sync(0xffffffffu, rs1, 1);
        rs1 += __shfl_xor_sync(0xffffffffu, rs1, 2);
        l0 = l0 * al0 + rs0;
        l1 = l1 * al1 + rs1;

        // O += P @ V (reg-resident P; V rows (2cc,2cc+1) = natural LDS.64)
#pragma unroll
        for (int ks = 0; ks < 8; ks++) {
            uint32_t a0 = __float_as_uint(Sacc[ks][0]);
            uint32_t a1 = __float_as_uint(Sacc[ks][2]);
            uint32_t a2 = __float_as_uint(Sacc[ks][1]);
            uint32_t a3 = __float_as_uint(Sacc[ks][3]);
#pragma unroll
            for (int nf = 0; nf < 8; nf++) {
                float2 bb = *(const float2*)(sV + (nf * 8 + rr) * VSTR + ks * 8 + 2 * cc);
                MMA_TF32(Oacc[nf][0], Oacc[nf][1], Oacc[nf][2], Oacc[nf][3],
                         a0, a1, a2, a3, __float_as_uint(bb.x), __float_as_uint(bb.y));
            }
        }
    }

    // epilogue
    float inv0 = 1.0f / l0, inv1 = 1.0f / l1;
#pragma unroll
    for (int nf = 0; nf < 8; nf++) {
        int c = h * DH + nf * 8 + cc * 2;
        size_t o0 = ((size_t)r0g * BZ + b) * D + c;
        size_t o1 = ((size_t)r1g * BZ + b) * D + c;
        float2 q0 = *(const float2*)&q[o0];
        float2 q1 = *(const float2*)&q[o1];
        *(float2*)&out[o0] = make_float2(q0.x + Oacc[nf][0] * inv0,
                                         q0.y + Oacc[nf][1] * inv0);
        *(float2*)&out[o1] = make_float2(q1.x + Oacc[nf][2] * inv1,
                                         q1.y + Oacc[nf][3] * inv1);
    }
}

// ---------------- launch ----------------------------------------------------
extern "C" void kernel_launch(void* const* d_in, const int* in_sizes, int n_in,
                              void* d_out, int out_size) {
    const float* query = (const float*)d_in[0];
    const float* seg   = (const float*)d_in[1];
    const float* Wq    = (const float*)d_in[2];
    const float* bq    = (const float*)d_in[3];
    const float* Wk    = (const float*)d_in[4];
    const float* bk    = (const float*)d_in[5];
    const float* Wv    = (const float*)d_in[6];
    const float* bv    = (const float*)d_in[7];
    float* out = (float*)d_out;

    const int PM_SMEM = 4 * CHUNK_BYTES;   // 73728
    cudaFuncSetAttribute(pm_kernel, cudaFuncAttributeMaxDynamicSharedMemorySize, PM_SMEM);
    cudaFuncSetAttribute(flash_kernel, cudaFuncAttributeMaxDynamicSharedMemorySize,
                         FSM_BYTES);

    prep_kernel<<<4864, 256>>>(query, Wq, Wk, Wv);
    pm_kernel<<<1280, 256, PM_SMEM>>>(seg, bq, bk, bv);
    flash_kernel<<<dim3(8, 64), 256, FSM_BYTES>>>(query, out);
}

// round 9
// speedup vs baseline: 8.4196x; 1.1793x over previous
#include <cuda_runtime.h>
#include <math.h>
#include <stdint.h>

#define LQ 1024
#define BZ 8
#define D  512
#define NH 8
#define DH 64
#define IOU_THR 0.2f
#define COS_THR 0.2f
#define NEGF -3.402823466e38f

#define SSTR 36   // pm smem stride (floats): 144B = 16 mod 128 -> LDSM conflict-free
#define FSTR 68   // flash Q/K stride: 272B = 16 mod 128 -> LDSM conflict-free
#define VSTR 72   // flash V stride: 288B = 32 mod 128 -> LDS.64 conflict-free

// ---------------- scratch (static device globals; no allocations) ----------
__device__ float g_hr[(size_t)BZ * LQ * D];                // tf32-rounded h (q layout)
__device__ float g_Wr[3 * 512 * 512];                      // tf32-rounded Wq|Wk|Wv
__device__ float g_Q[(size_t)BZ * LQ * D];                 // tf32-rounded
__device__ float g_K[(size_t)BZ * LQ * D];
__device__ float g_Vt[(size_t)BZ * NH * DH * LQ];          // [bh][dh][Lq], tf32-rounded
__device__ float g_norm[BZ * LQ];
__device__ unsigned char g_mask[(size_t)BZ * LQ * LQ];     // 1 = masked
__device__ unsigned char g_live[BZ * 8 * 16];              // [b][i128][j64] any-adj flag

__device__ __forceinline__ float tf32r(float x) {
    float y;
    asm("cvt.rna.tf32.f32 %0, %1;" : "=f"(y) : "f"(x));
    return y;
}
__device__ __forceinline__ uint32_t smem_u32(const void* p) {
    uint32_t a;
    asm("{ .reg .u64 t; cvta.to.shared.u64 t, %1; cvt.u32.u64 %0, t; }"
        : "=r"(a) : "l"(p));
    return a;
}

#define MMA_TF32(c0, c1, c2, c3, a0, a1, a2, a3, b0, b1) \
    asm volatile("mma.sync.aligned.m16n8k8.row.col.f32.tf32.tf32.f32 " \
        "{%0,%1,%2,%3}, {%4,%5,%6,%7}, {%8,%9}, {%0,%1,%2,%3};" \
        : "+f"(c0), "+f"(c1), "+f"(c2), "+f"(c3) \
        : "r"(a0), "r"(a1), "r"(a2), "r"(a3), "r"(b0), "r"(b1))

#define LDSM_X4(d0, d1, d2, d3, addr) \
    asm volatile("ldmatrix.sync.aligned.m8n8.x4.shared.b16 {%0,%1,%2,%3}, [%4];" \
        : "=r"(d0), "=r"(d1), "=r"(d2), "=r"(d3) : "r"(addr))

#define CPASYNC16(dst, src) \
    asm volatile("cp.async.ca.shared.global [%0], [%1], 16;" \
                 :: "r"(dst), "l"(src) : "memory")
#define CPCOMMIT() asm volatile("cp.async.commit_group;" ::: "memory")
#define CPWAIT(n)  asm volatile("cp.async.wait_group %0;" :: "n"(n) : "memory")

__device__ __forceinline__ float warp_sum(float v) {
#pragma unroll
    for (int o = 16; o > 0; o >>= 1) v += __shfl_xor_sync(0xffffffffu, v, o);
    return v;
}

// ==================== tf32 GEMM core: LDSM frags + cp.async =================
__device__ __forceinline__ void mma_chunk_ldsm(uint32_t As_u, uint32_t Bs_u,
                                               int wm, int wn, int lane,
                                               float (&acc)[4][4][4]) {
    const uint32_t a_base = As_u +
        ((wm * 64 + (lane & 15)) * SSTR + ((lane >> 4) & 1) * 4) * 4;
    const uint32_t b_base = Bs_u +
        (((wn * 4 + ((lane >> 4) & 1)) * 8 + (lane & 7)) * SSTR + ((lane >> 3) & 1) * 4) * 4;
#pragma unroll
    for (int ks = 0; ks < 4; ks++) {
        uint32_t a[4][4];
#pragma unroll
        for (int mf = 0; mf < 4; mf++)
            LDSM_X4(a[mf][0], a[mf][1], a[mf][2], a[mf][3],
                    a_base + (mf * 16 * SSTR) * 4 + ks * 32);
        uint32_t bfr[2][4];
#pragma unroll
        for (int p = 0; p < 2; p++)
            LDSM_X4(bfr[p][0], bfr[p][1], bfr[p][2], bfr[p][3],
                    b_base + (p * 16 * SSTR) * 4 + ks * 32);
#pragma unroll
        for (int mf = 0; mf < 4; mf++)
#pragma unroll
            for (int nf = 0; nf < 4; nf++) {
                uint32_t b0 = bfr[nf >> 1][(nf & 1) * 2];
                uint32_t b1 = bfr[nf >> 1][(nf & 1) * 2 + 1];
                MMA_TF32(acc[mf][nf][0], acc[mf][nf][1], acc[mf][nf][2], acc[mf][nf][3],
                         a[mf][0], a[mf][1], a[mf][2], a[mf][3], b0, b1);
            }
    }
}

#define CHUNK_BYTES (128 * SSTR * 4)

__device__ __forceinline__ void issue_chunk(uint32_t base,
                                            const float* __restrict__ Ab, int Astr,
                                            const float* __restrict__ Bb, int Bstr,
                                            int it, int tid) {
    const int p = it & 1;
    const uint32_t aoff = base + (uint32_t)(p * CHUNK_BYTES);
    const uint32_t boff = base + (uint32_t)((2 + p) * CHUNK_BYTES);
#pragma unroll
    for (int i = 0; i < 4; i++) {
        int idx = tid + i * 256;
        int r = idx >> 3, c4 = idx & 7;
        CPASYNC16(aoff + (r * SSTR + c4 * 4) * 4, Ab + (size_t)r * Astr + it * 32 + c4 * 4);
        CPASYNC16(boff + (r * SSTR + c4 * 4) * 4, Bb + (size_t)r * Bstr + it * 32 + c4 * 4);
    }
}

template <int NCH>
__device__ __forceinline__ void gemm_async(const float* __restrict__ Ab, int Astr,
                                           const float* __restrict__ Bb, int Bstr,
                                           float* smem, float (&acc)[4][4][4]) {
    const int tid = threadIdx.x;
    const int w = tid >> 5, lane = tid & 31;
    const int wm = w & 1, wn = w >> 1;
    const uint32_t base = smem_u32(smem);
    issue_chunk(base, Ab, Astr, Bb, Bstr, 0, tid);
    CPCOMMIT();
    for (int it = 0; it < NCH; ++it) {
        const int p = it & 1;
        if (it + 1 < NCH) {
            issue_chunk(base, Ab, Astr, Bb, Bstr, it + 1, tid);
            CPCOMMIT();
            CPWAIT(1);
        } else {
            CPWAIT(0);
        }
        __syncthreads();
        mma_chunk_ldsm(base + p * CHUNK_BYTES, base + (2 + p) * CHUNK_BYTES,
                       wm, wn, lane, acc);
        __syncthreads();
    }
}

// ---------------- prep: norms + tf32-rounded h and W ------------------------
__global__ void prep_kernel(const float* __restrict__ q,
                            const float* __restrict__ Wq,
                            const float* __restrict__ Wk,
                            const float* __restrict__ Wv) {
    const int bid = blockIdx.x, tid = threadIdx.x;
    if (bid < 4096) {
        const int half = tid >> 7;
        const int t = tid & 127;
        const int row = bid * 2 + half;
        const int b = row >> 10, l = row & 1023;
        const size_t o = ((size_t)l * BZ + b) * D + t * 4;
        float4 v = *(const float4*)(q + o);
        *(float4*)(g_hr + o) = make_float4(tf32r(v.x), tf32r(v.y), tf32r(v.z), tf32r(v.w));
        float s = v.x * v.x + v.y * v.y + v.z * v.z + v.w * v.w;
        s = warp_sum(s);
        __shared__ float red[8];
        if ((t & 31) == 0) red[half * 4 + (t >> 5)] = s;
        __syncthreads();
        if (t == 0) {
            float tot = red[half * 4] + red[half * 4 + 1] +
                        red[half * 4 + 2] + red[half * 4 + 3];
            g_norm[row] = fmaxf(sqrtf(tot), 1e-8f);
        }
    } else {
        const int idx = (bid - 4096) * 256 + tid;
        const int which = idx >> 16;
        const int off = (idx & 65535) * 4;
        const float* W = (which == 0) ? Wq : (which == 1) ? Wk : Wv;
        float4 v = *(const float4*)(W + off);
        *(float4*)(g_Wr + which * 262144 + off) =
            make_float4(tf32r(v.x), tf32r(v.y), tf32r(v.z), tf32r(v.w));
    }
}

// ================ fused proj (bid<768) + mask-triangle (bid>=768) ===========
// dynamic smem: 4 chunk buffers (A0 A1 B0 B1) = 73728 bytes
__global__ __launch_bounds__(256, 2) void pm_kernel(
    const float* __restrict__ seg,
    const float* __restrict__ bq, const float* __restrict__ bk, const float* __restrict__ bv) {
    extern __shared__ float smp[];
    const int tid = threadIdx.x;
    const int w = tid >> 5, lane = tid & 31;
    const int wm = w & 1, wn = w >> 1;
    const int bid = blockIdx.x;

    if (bid < 768) {   // ---------------- projection path ----------------
        const int which = bid >> 8;
        const int rem = bid & 255;
        const int col0 = (rem & 3) * 128;
        const int y = rem >> 2;
        const int b = y >> 3;
        const int i0 = (y & 7) * 128;
        const float* bias = (which == 0) ? bq : (which == 1) ? bk : bv;

        float acc[4][4][4] = {};
        const float* Ab = g_hr + (size_t)i0 * (BZ * D) + (size_t)b * D;
        const float* Bb = g_Wr + which * 262144 + (size_t)col0 * D;
        gemm_async<D / 32>(Ab, BZ * D, Bb, D, smp, acc);

        const int rbase = wm * 64 + (lane >> 2);
        const int cbase = wn * 32 + (lane & 3) * 2;
        if (which < 2) {
            float* out = (which == 0) ? g_Q : g_K;
#pragma unroll
            for (int mf = 0; mf < 4; mf++) {
                int r0 = i0 + rbase + mf * 16;
#pragma unroll
                for (int nf = 0; nf < 4; nf++) {
                    int c = col0 + cbase + nf * 8;
                    float2 bb = *(const float2*)&bias[c];
                    *(float2*)&out[((size_t)(b * LQ + r0)) * D + c] =
                        make_float2(tf32r(acc[mf][nf][0] + bb.x),
                                    tf32r(acc[mf][nf][1] + bb.y));
                    *(float2*)&out[((size_t)(b * LQ + r0 + 8)) * D + c] =
                        make_float2(tf32r(acc[mf][nf][2] + bb.x),
                                    tf32r(acc[mf][nf][3] + bb.y));
                }
            }
        } else {
#pragma unroll
            for (int mf = 0; mf < 4; mf++) {
                int r0 = i0 + rbase + mf * 16;
#pragma unroll
                for (int nf = 0; nf < 4; nf++) {
                    int n = col0 + cbase + nf * 8;
                    float2 bb = *(const float2*)&bias[n];
                    size_t o0 = ((size_t)(b * NH + (n >> 6)) * DH + (n & 63)) * LQ;
                    size_t o1 = ((size_t)(b * NH + ((n + 1) >> 6)) * DH + ((n + 1) & 63)) * LQ;
                    g_Vt[o0 + r0]     = tf32r(acc[mf][nf][0] + bb.x);
                    g_Vt[o1 + r0]     = tf32r(acc[mf][nf][1] + bb.y);
                    g_Vt[o0 + r0 + 8] = tf32r(acc[mf][nf][2] + bb.x);
                    g_Vt[o1 + r0 + 8] = tf32r(acc[mf][nf][3] + bb.y);
                }
            }
        }
    } else {   // -------- mask path: only upper-triangle tile pairs I<=J ----
        const int mb = bid - 768;
        const int b = mb / 36;
        int t = mb % 36;
        int I = 0;
        while (t >= 8 - I) { t -= 8 - I; I++; }
        const int J = I + t;
        const int i0 = I * 128, j0 = J * 128;

        float acc[4][4][4] = {};
        const float* Ab = g_hr + (size_t)i0 * (BZ * D) + (size_t)b * D;
        const float* Bb = g_hr + (size_t)j0 * (BZ * D) + (size_t)b * D;
        gemm_async<D / 32>(Ab, BZ * D, Bb, BZ * D, smp, acc);

        __shared__ unsigned int liveflag[4];   // [0,1]=col halves, [2,3]=row halves
        if (tid < 4) liveflag[tid] = 0;
        __syncthreads();

        float4* auxr = (float4*)smp;
        float4* auxc = (float4*)(smp + 512);
        unsigned char* sT = (unsigned char*)(smp + 2048);   // 128 x 144 transpose tile
        const float* sgb = seg + (size_t)b * LQ * 2;
        if (tid < 128) {
            int r = i0 + tid;
            float2 sg = *(const float2*)(sgb + r * 2);
            auxr[tid] = make_float4(g_norm[b * LQ + r], sg.x - 0.5f * sg.y,
                                    sg.x + 0.5f * sg.y, sg.y);
        } else {
            int tt = tid - 128;
            int c = j0 + tt;
            float2 sg = *(const float2*)(sgb + c * 2);
            auxc[tt] = make_float4(g_norm[b * LQ + c], sg.x - 0.5f * sg.y,
                                   sg.x + 0.5f * sg.y, sg.y);
        }
        __syncthreads();

        const int rbase = wm * 64 + (lane >> 2);
        const int cbase = wn * 32 + (lane & 3) * 2;
        unsigned int any = 0;
#pragma unroll
        for (int mf = 0; mf < 4; mf++) {
#pragma unroll
            for (int half = 0; half < 2; half++) {
                int rl_ = rbase + mf * 16 + half * 8;
                float4 ar = auxr[rl_];
                int rg = i0 + rl_;
#pragma unroll
                for (int nf = 0; nf < 4; nf++) {
                    int cl_ = cbase + nf * 8;
                    uchar2 mm;
#pragma unroll
                    for (int e = 0; e < 2; e++) {
                        float4 ac = auxc[cl_ + e];
                        float cosv = acc[mf][nf][half * 2 + e] / (ar.x * ac.x);
                        float inter = fmaxf(fminf(ar.z, ac.z) - fmaxf(ar.y, ac.y), 0.f);
                        float iou = inter / (ar.w + ac.w - inter);
                        int cg = j0 + cl_ + e;
                        bool adj = (cosv > COS_THR) && ((iou <= IOU_THR) || (rg == cg));
                        any |= (unsigned)adj;
                        unsigned char mv = adj ? 0 : 1;
                        if (e == 0) mm.x = mv; else mm.y = mv;
                        sT[(cl_ + e) * 144 + rl_] = mv;     // transposed stage
                    }
                    *(uchar2*)&g_mask[((size_t)(b * LQ + rg)) * LQ + j0 + cl_] = mm;
                }
            }
        }
        if (any) {
            atomicOr(&liveflag[wn >> 1], 1u);
            atomicOr(&liveflag[2 + wm], 1u);
        }
        __syncthreads();

        if (I != J) {
            // write transposed block rows (coalesced 16B)
#pragma unroll
            for (int i = 0; i < 4; i++) {
                int idx = tid + i * 256;
                int c = idx >> 3, g = idx & 7;      // c: 0..127 rows of transposed tile
                *(uint4*)&g_mask[((size_t)(b * LQ + j0 + c)) * LQ + i0 + g * 16] =
                    *(const uint4*)&sT[c * 144 + g * 16];
            }
            if (tid < 2)
                g_live[(b * 8 + J) * 16 + I * 2 + tid] = (unsigned char)liveflag[2 + tid];
        }
        if (tid < 2)
            g_live[(b * 8 + I) * 16 + J * 2 + tid] = (unsigned char)liveflag[tid];
    }
}

// ==================== fused attention (flash, skip + cp.async prefetch) =====
// smem floats: sQ[0,8704) sK0[8704,13056) sK1[13056,17408) sV0[17408,22016) sV1[22016,26624)
#define FSM_BYTES (26624 * 4)

__device__ __forceinline__ void issue_kv(float* sm, int p, int jt,
                                         int b, int bh, int h, int tid) {
    const int j0 = jt * 64;
    const uint32_t koff = smem_u32(sm + 8704 + p * 4352);
    const uint32_t voff = smem_u32(sm + 17408 + p * 4608);
#pragma unroll
    for (int i = 0; i < 4; i++) {
        int idx = tid + i * 256;
        int r = idx >> 4, g = idx & 15;
        CPASYNC16(koff + (r * FSTR + g * 4) * 4,
                  g_K + ((size_t)(b * LQ + j0 + r)) * D + h * DH + g * 4);
        CPASYNC16(voff + (r * VSTR + g * 4) * 4,
                  g_Vt + ((size_t)bh * DH + r) * LQ + j0 + g * 4);
    }
}

__global__ __launch_bounds__(256, 2) void flash_kernel(const float* __restrict__ q,
                                                       float* __restrict__ out) {
    extern __shared__ float sm[];
    float* sQ = sm;

    const int tid = threadIdx.x;
    const int w = tid >> 5, lane = tid & 31;
    const int rr = lane >> 2, cc = lane & 3;
    const int bh = blockIdx.y, b = bh >> 3, h = bh & 7;
    const int i0 = blockIdx.x * 128;
    const int wbase = w * 16;

    __shared__ int s_list[16];
    __shared__ int s_nlive;

    // stage Q (pre-rounded)
#pragma unroll
    for (int i = 0; i < 8; i++) {
        int idx = tid + i * 256;
        int r = idx >> 4, c4 = idx & 15;
        *(float4*)&sQ[r * FSTR + c4 * 4] =
            *(const float4*)&g_Q[((size_t)(b * LQ + i0 + r)) * D + h * DH + c4 * 4];
    }
    // build compact live-tile list
    if (w == 0) {
        unsigned f = 0;
        if (lane < 16) f = g_live[(b * 8 + (i0 >> 7)) * 16 + lane];
        unsigned bal = __ballot_sync(0xffffffffu, f != 0) & 0xffffu;
        if (lane < 16 && f) s_list[__popc(bal & ((1u << lane) - 1))] = lane;
        if (lane == 0) s_nlive = __popc(bal);
    }
    __syncthreads();
    const int nlive = s_nlive;

    const uint32_t q_base = smem_u32(sQ) +
        ((wbase + (lane & 15)) * FSTR + ((lane >> 4) & 1) * 4) * 4;
    const uint32_t k_base0 = smem_u32(sm + 8704) +
        ((((lane >> 4) & 1) * 8 + (lane & 7)) * FSTR + ((lane >> 3) & 1) * 4) * 4;

    float Oacc[8][4] = {};
    float m0 = NEGF, m1 = NEGF, l0 = 0.f, l1 = 0.f;
    const int r0g = i0 + wbase + rr, r1g = r0g + 8;
    const unsigned char* mrow0 = g_mask + ((size_t)(b * LQ + r0g)) * LQ;
    const unsigned char* mrow1 = g_mask + ((size_t)(b * LQ + r1g)) * LQ;

    issue_kv(sm, 0, s_list[0], b, bh, h, tid);
    CPCOMMIT();

    for (int li = 0; li < nlive; li++) {
        const int p = li & 1;
        const int j0 = s_list[li] * 64;
        if (li + 1 < nlive) {
            issue_kv(sm, p ^ 1, s_list[li + 1], b, bh, h, tid);
            CPCOMMIT();
            CPWAIT(1);
        } else {
            CPWAIT(0);
        }
        __syncthreads();
        const uint32_t k_base = k_base0 + p * 17408;
        const float* sV = sm + 17408 + p * 4608;

        // S = Q K^T via LDSM fragments
        float Sacc[8][4] = {};
#pragma unroll
        for (int ks = 0; ks < 8; ks++) {
            uint32_t a0, a1, a2, a3;
            LDSM_X4(a0, a1, a2, a3, q_base + ks * 32);
#pragma unroll
            for (int pp = 0; pp < 4; pp++) {
                uint32_t f0, f1, f2, f3;
                LDSM_X4(f0, f1, f2, f3, k_base + (pp * 16 * FSTR) * 4 + ks * 32);
                MMA_TF32(Sacc[pp * 2][0], Sacc[pp * 2][1], Sacc[pp * 2][2], Sacc[pp * 2][3],
                         a0, a1, a2, a3, f0, f1);
                MMA_TF32(Sacc[pp * 2 + 1][0], Sacc[pp * 2 + 1][1],
                         Sacc[pp * 2 + 1][2], Sacc[pp * 2 + 1][3],
                         a0, a1, a2, a3, f2, f3);
            }
        }

        // scale + mask + tile row max
        float mx0 = NEGF, mx1 = NEGF;
#pragma unroll
        for (int nf = 0; nf < 8; nf++) {
            int c = j0 + nf * 8 + cc * 2;
            uchar2 ma = *(const uchar2*)&mrow0[c];
            uchar2 mb = *(const uchar2*)&mrow1[c];
            Sacc[nf][0] = ma.x ? NEGF : Sacc[nf][0] * 0.125f;
            Sacc[nf][1] = ma.y ? NEGF : Sacc[nf][1] * 0.125f;
            Sacc[nf][2] = mb.x ? NEGF : Sacc[nf][2] * 0.125f;
            Sacc[nf][3] = mb.y ? NEGF : Sacc[nf][3] * 0.125f;
            mx0 = fmaxf(mx0, fmaxf(Sacc[nf][0], Sacc[nf][1]));
            mx1 = fmaxf(mx1, fmaxf(Sacc[nf][2], Sacc[nf][3]));
        }
        mx0 = fmaxf(mx0, __shfl_xor_sync(0xffffffffu, mx0, 1));
        mx0 = fmaxf(mx0, __shfl_xor_sync(0xffffffffu, mx0, 2));
        mx1 = fmaxf(mx1, __shfl_xor_sync(0xffffffffu, mx1, 1));
        mx1 = fmaxf(mx1, __shfl_xor_sync(0xffffffffu, mx1, 2));

        float nm0 = fmaxf(m0, mx0), nm1 = fmaxf(m1, mx1);
        float al0 = __expf(m0 - nm0), al1 = __expf(m1 - nm1);
        m0 = nm0; m1 = nm1;

        float rs0 = 0.f, rs1 = 0.f;
#pragma unroll
        for (int nf = 0; nf < 8; nf++) {
            float p00 = __expf(Sacc[nf][0] - nm0);
            float p01 = __expf(Sacc[nf][1] - nm0);
            float p10 = __expf(Sacc[nf][2] - nm1);
            float p11 = __expf(Sacc[nf][3] - nm1);
            rs0 += p00 + p01; rs1 += p10 + p11;
            Sacc[nf][0] = tf32r(p00); Sacc[nf][1] = tf32r(p01);
            Sacc[nf][2] = tf32r(p10); Sacc[nf][3] = tf32r(p11);
            Oacc[nf][0] *= al0; Oacc[nf][1] *= al0;
            Oacc[nf][2] *= al1; Oacc[nf][3] *= al1;
        }
        rs0 += __shfl_xor_sync(0xffffffffu, rs0, 1);
        rs0 += __shfl_xor_sync(0xffffffffu, rs0, 2);
        rs1 += __shfl_xor_sync(0xffffffffu, rs1, 1);
        rs1 += __shfl_xor_sync(0xffffffffu, rs1, 2);
        l0 = l0 * al0 + rs0;
        l1 = l1 * al1 + rs1;

        // O += P @ V (reg-resident P; V rows (2cc,2cc+1) = natural LDS.64)
#pragma unroll
        for (int ks = 0; ks < 8; ks++) {
            uint32_t a0 = __float_as_uint(Sacc[ks][0]);
            uint32_t a1 = __float_as_uint(Sacc[ks][2]);
            uint32_t a2 = __float_as_uint(Sacc[ks][1]);
            uint32_t a3 = __float_as_uint(Sacc[ks][3]);
#pragma unroll
            for (int nf = 0; nf < 8; nf++) {
                float2 bb = *(const float2*)(sV + (nf * 8 + rr) * VSTR + ks * 8 + 2 * cc);
                MMA_TF32(Oacc[nf][0], Oacc[nf][1], Oacc[nf][2], Oacc[nf][3],
                         a0, a1, a2, a3, __float_as_uint(bb.x), __float_as_uint(bb.y));
            }
        }
        __syncthreads();
    }

    // epilogue
    float inv0 = 1.0f / l0, inv1 = 1.0f / l1;
#pragma unroll
    for (int nf = 0; nf < 8; nf++) {
        int c = h * DH + nf * 8 + cc * 2;
        size_t o0 = ((size_t)r0g * BZ + b) * D + c;
        size_t o1 = ((size_t)r1g * BZ + b) * D + c;
        float2 q0 = *(const float2*)&q[o0];
        float2 q1 = *(const float2*)&q[o1];
        *(float2*)&out[o0] = make_float2(q0.x + Oacc[nf][0] * inv0,
                                         q0.y + Oacc[nf][1] * inv0);
        *(float2*)&out[o1] = make_float2(q1.x + Oacc[nf][2] * inv1,
                                         q1.y + Oacc[nf][3] * inv1);
    }
}

// ---------------- launch ----------------------------------------------------
extern "C" void kernel_launch(void* const* d_in, const int* in_sizes, int n_in,
                              void* d_out, int out_size) {
    const float* query = (const float*)d_in[0];
    const float* seg   = (const float*)d_in[1];
    const float* Wq    = (const float*)d_in[2];
    const float* bq    = (const float*)d_in[3];
    const float* Wk    = (const float*)d_in[4];
    const float* bk    = (const float*)d_in[5];
    const float* Wv    = (const float*)d_in[6];
    const float* bv    = (const float*)d_in[7];
    float* out = (float*)d_out;

    const int PM_SMEM = 4 * CHUNK_BYTES;   // 73728
    cudaFuncSetAttribute(pm_kernel, cudaFuncAttributeMaxDynamicSharedMemorySize, PM_SMEM);
    cudaFuncSetAttribute(flash_kernel, cudaFuncAttributeMaxDynamicSharedMemorySize,
                         FSM_BYTES);

    prep_kernel<<<4864, 256>>>(query, Wq, Wk, Wv);
    pm_kernel<<<1056, 256, PM_SMEM>>>(seg, bq, bk, bv);
    flash_kernel<<<dim3(8, 64), 256, FSM_BYTES>>>(query, out);
}